// round 13
// baseline (speedup 1.0000x reference)
#include <cuda_runtime.h>
#include <cuda_bf16.h>
#include <math.h>

#define Nn 8192
#define Dn 2048
#define Kn 256
#define NBLK 148
#define ROWS_PB 14            // 148 * 14 = 2072 >= 2048

typedef unsigned long long ull;
typedef unsigned int u32;
typedef unsigned short u16;

// ---------------- f32x2 packed FMA helpers (Blackwell FFMA2) ----------------
__device__ __forceinline__ ull splat2(float s) {
    ull d;
    asm("mov.b64 %0, {%1, %1};" : "=l"(d) : "r"(__float_as_uint(s)));
    return d;
}
__device__ __forceinline__ void fma2(ull& d, ull a, ull b) {
    asm("fma.rn.f32x2 %0, %1, %2, %0;" : "+l"(d) : "l"(a), "l"(b));
}

// ---------------- device scratch (static: no allocation allowed) ----------------
__device__ float g_C[(size_t)Dn * Dn];          // 16 MB  C = x^T x (L2-resident)
__device__ __nv_bfloat16 g_xh[(size_t)Nn * Dn]; // 32 MB hi split
__device__ __nv_bfloat16 g_xl[(size_t)Nn * Dn]; // 32 MB lo split
__device__ float g_Vt[(size_t)Kn * Dn];
__device__ float g_VnT[(size_t)Dn * Kn];
__device__ float g_a[Dn];
__device__ float g_c1[2][Kn];
__device__ float g_c3[2][Kn];
__device__ float g_g[Kn];
__device__ float g_d0[Kn];
__device__ float g_dn2[2];
__device__ float g_uv[2];
// barrier v5: 8 arrival counters 1KB apart (distinct LTS slices via bits 10-12)
__device__ __align__(128) unsigned g_cnt[8 * 256];
__device__ __align__(128) unsigned g_done;

// ---------------- grid barrier v5: sharded arrivals + SELF-poll ---------------
// L2-atomic law: n_conc red ops to ONE address drain at ~27 cyc/op -> 148
// arrivals = ~4K cyc. Sharding over 8 counters cuts the drain to ~19*27=500.
// Each block polls ALL 8 counters itself (MLP-8 acquire loads, no master hop).
// Counters 0..3 receive 19 arrivals/gen (bid&7 < 4), counters 4..7 receive 18.
__device__ __forceinline__ void gbar(unsigned& gen, int cshard) {
    ++gen;
    __syncthreads();
    if (threadIdx.x == 0) {
        asm volatile("red.release.gpu.global.add.u32 [%0], 1;"
                     :: "l"(&g_cnt[cshard * 256]) : "memory");
        const unsigned t19 = gen * 19u, t18 = gen * 18u;
        bool ok;
        do {
            unsigned v[8];
            #pragma unroll
            for (int c = 0; c < 8; ++c)
                asm volatile("ld.acquire.gpu.global.u32 %0, [%1];"
                             : "=r"(v[c]) : "l"(&g_cnt[c * 256]) : "memory");
            ok = true;
            #pragma unroll
            for (int c = 0; c < 8; ++c)
                ok &= ((int)(v[c] - (c < 4 ? t19 : t18)) >= 0);
        } while (!ok);
    }
    __syncthreads();
}

// ---------------- split x into bf16 hi + lo ----------------
__global__ void __launch_bounds__(256) splitx_kernel(const float* __restrict__ x) {
    const int stride = gridDim.x * 256;
    for (int i = blockIdx.x * 256 + threadIdx.x; i < Nn * Dn / 4; i += stride) {
        float4 v = ((const float4*)x)[i];
        __nv_bfloat16 h0 = __float2bfloat16(v.x);
        __nv_bfloat16 h1 = __float2bfloat16(v.y);
        __nv_bfloat16 h2 = __float2bfloat16(v.z);
        __nv_bfloat16 h3 = __float2bfloat16(v.w);
        __nv_bfloat16 l0 = __float2bfloat16(v.x - __bfloat162float(h0));
        __nv_bfloat16 l1 = __float2bfloat16(v.y - __bfloat162float(h1));
        __nv_bfloat16 l2 = __float2bfloat16(v.z - __bfloat162float(h2));
        __nv_bfloat16 l3 = __float2bfloat16(v.w - __bfloat162float(h3));
        ushort4 hh, ll;
        hh.x = *(u16*)&h0; hh.y = *(u16*)&h1; hh.z = *(u16*)&h2; hh.w = *(u16*)&h3;
        ll.x = *(u16*)&l0; ll.y = *(u16*)&l1; ll.z = *(u16*)&l2; ll.w = *(u16*)&l3;
        ((ushort4*)g_xh)[i] = hh;
        ((ushort4*)g_xl)[i] = ll;
    }
}

// ---------------- prep: transpose V0 -> Vt, per-column norms d0 ----------------
__global__ void __launch_bounds__(256) prep_kernel(const float* __restrict__ V0) {
    __shared__ float sb[8];
    int k = blockIdx.x;
    float s = 0.f;
    for (int d = threadIdx.x; d < Dn; d += 256) {
        float v = V0[(size_t)d * Kn + k];
        g_Vt[(size_t)k * Dn + d] = v;
        s += v * v;
    }
    #pragma unroll
    for (int o = 16; o; o >>= 1) s += __shfl_down_sync(~0u, s, o);
    if ((threadIdx.x & 31) == 0) sb[threadIdx.x >> 5] = s;
    __syncthreads();
    if (threadIdx.x == 0) {
        float t = 0.f;
        #pragma unroll
        for (int w = 0; w < 8; ++w) t += sb[w];
        g_d0[k] = sqrtf(t);
    }
}

// ---------------- tensor-core helpers ----------------
__device__ __forceinline__ void ldsm4t(u32& r0, u32& r1, u32& r2, u32& r3, u32 addr) {
    asm volatile("ldmatrix.sync.aligned.m8n8.x4.trans.shared.b16 {%0,%1,%2,%3}, [%4];"
                 : "=r"(r0), "=r"(r1), "=r"(r2), "=r"(r3) : "r"(addr));
}
__device__ __forceinline__ void mma16816(float* c, const u32* a, const u32* b) {
    asm volatile(
        "mma.sync.aligned.m16n8k16.row.col.f32.bf16.bf16.f32 "
        "{%0,%1,%2,%3}, {%4,%5,%6,%7}, {%8,%9}, {%0,%1,%2,%3};"
        : "+f"(c[0]), "+f"(c[1]), "+f"(c[2]), "+f"(c[3])
        : "r"(a[0]), "r"(a[1]), "r"(a[2]), "r"(a[3]), "r"(b[0]), "r"(b[1]));
}

// ---------------- C = xh^T xh + xh^T xl + xl^T xh (tensor cores) ---------------
__global__ void __launch_bounds__(256) gemmC_tc_kernel() {
    __shared__ __align__(16) char smt[2][4][16 * 256];

    int rem = blockIdx.x, bi = 0, width = 16;
    while (rem >= width) { rem -= width; ++bi; --width; }
    int bj = bi + rem;

    const int tid = threadIdx.x;
    const int warp = tid >> 5, lane = tid & 31;
    const int wm = warp >> 2, wn = warp & 3;

    float acc[4][4][4];
    #pragma unroll
    for (int i = 0; i < 4; ++i)
        #pragma unroll
        for (int j = 0; j < 4; ++j)
            #pragma unroll
            for (int r = 0; r < 4; ++r) acc[i][j][r] = 0.f;

    const int ln = tid >> 4;
    const int lc = tid & 15;
    const int sw_off = ln * 256 + ((lc ^ (ln & 7)) << 4);
    const size_t gA = (size_t)ln * Dn + bi * 128 + lc * 8;
    const size_t gB = (size_t)ln * Dn + bj * 128 + lc * 8;

    const int q = lane >> 3, r8 = lane & 7;
    int a_colh[4], a_row[4];
    #pragma unroll
    for (int i = 0; i < 4; ++i) {
        int m_off = (q & 1) << 3, k_off = (q >> 1) << 3;
        a_colh[i] = wm * 64 + (i << 4) + m_off;
        a_row[i]  = k_off + r8;
    }
    int b_colh[2], b_row[2];
    #pragma unroll
    for (int p = 0; p < 2; ++p) {
        int n_off = (p << 4) + ((q >> 1) << 3);
        int k_off = (q & 1) << 3;
        b_colh[p] = wn * 32 + n_off;
        b_row[p]  = k_off + r8;
    }
    u32 aoff[4], boff[2];
    #pragma unroll
    for (int i = 0; i < 4; ++i)
        aoff[i] = a_row[i] * 256 + ((((u32)a_colh[i] >> 3) ^ (a_row[i] & 7)) << 4);
    #pragma unroll
    for (int p = 0; p < 2; ++p)
        boff[p] = b_row[p] * 256 + ((((u32)b_colh[p] >> 3) ^ (b_row[p] & 7)) << 4);

    const u32 smem_base = (u32)__cvta_generic_to_shared(&smt[0][0][0]);

    uint4 pf0, pf1, pf2, pf3;
    pf0 = *(const uint4*)(g_xh + gA);
    pf1 = *(const uint4*)(g_xl + gA);
    pf2 = *(const uint4*)(g_xh + gB);
    pf3 = *(const uint4*)(g_xl + gB);
    *(uint4*)(smt[0][0] + sw_off) = pf0;
    *(uint4*)(smt[0][1] + sw_off) = pf1;
    *(uint4*)(smt[0][2] + sw_off) = pf2;
    *(uint4*)(smt[0][3] + sw_off) = pf3;
    __syncthreads();

    int buf = 0;
    for (int n0 = 0; n0 < Nn; n0 += 16) {
        const bool more = (n0 + 16 < Nn);
        if (more) {
            size_t adv = (size_t)(n0 + 16) * Dn;
            pf0 = *(const uint4*)(g_xh + gA + adv);
            pf1 = *(const uint4*)(g_xl + gA + adv);
            pf2 = *(const uint4*)(g_xh + gB + adv);
            pf3 = *(const uint4*)(g_xl + gB + adv);
        }
        const u32 tb = smem_base + buf * (4 * 4096);
        u32 Ah[4][4], Al[4][4], Bh[4][2], Bl[4][2];
        #pragma unroll
        for (int i = 0; i < 4; ++i) {
            ldsm4t(Ah[i][0], Ah[i][1], Ah[i][2], Ah[i][3], tb + 0 * 4096 + aoff[i]);
            ldsm4t(Al[i][0], Al[i][1], Al[i][2], Al[i][3], tb + 1 * 4096 + aoff[i]);
        }
        #pragma unroll
        for (int p = 0; p < 2; ++p) {
            ldsm4t(Bh[2 * p][0], Bh[2 * p][1], Bh[2 * p + 1][0], Bh[2 * p + 1][1],
                   tb + 2 * 4096 + boff[p]);
            ldsm4t(Bl[2 * p][0], Bl[2 * p][1], Bl[2 * p + 1][0], Bl[2 * p + 1][1],
                   tb + 3 * 4096 + boff[p]);
        }
        #pragma unroll
        for (int i = 0; i < 4; ++i)
            #pragma unroll
            for (int j = 0; j < 4; ++j) {
                mma16816(acc[i][j], Ah[i], Bh[j]);
                mma16816(acc[i][j], Ah[i], Bl[j]);
                mma16816(acc[i][j], Al[i], Bh[j]);
            }
        if (more) {
            int nb = buf ^ 1;
            *(uint4*)(smt[nb][0] + sw_off) = pf0;
            *(uint4*)(smt[nb][1] + sw_off) = pf1;
            *(uint4*)(smt[nb][2] + sw_off) = pf2;
            *(uint4*)(smt[nb][3] + sw_off) = pf3;
        }
        __syncthreads();
        buf ^= 1;
    }

    const int row0 = lane >> 2, col0 = (lane & 3) * 2;
    #pragma unroll
    for (int i = 0; i < 4; ++i) {
        #pragma unroll
        for (int j = 0; j < 4; ++j) {
            int gi = bi * 128 + wm * 64 + i * 16 + row0;
            int gj = bj * 128 + wn * 32 + j * 8 + col0;
            *(float2*)(g_C + (size_t)gi * Dn + gj) =
                make_float2(acc[i][j][0], acc[i][j][1]);
            *(float2*)(g_C + (size_t)(gi + 8) * Dn + gj) =
                make_float2(acc[i][j][2], acc[i][j][3]);
            if (bi != bj) {
                g_C[(size_t)gj * Dn + gi]           = acc[i][j][0];
                g_C[(size_t)(gj + 1) * Dn + gi]     = acc[i][j][1];
                g_C[(size_t)gj * Dn + gi + 8]       = acc[i][j][2];
                g_C[(size_t)(gj + 1) * Dn + gi + 8] = acc[i][j][3];
            }
        }
    }
}

// ---------------- persistent sequential CCIPCA solve ----------------
__global__ void __launch_bounds__(256) solve_kernel() {
    extern __shared__ __align__(16) float s_dyn[];
    float* s_C   = s_dyn;
    float* s_WT  = s_dyn + ROWS_PB * Dn;
    float* s_VnT = s_dyn + ROWS_PB * Dn + ROWS_PB * Kn;
    __shared__ __align__(16) float s_a[Dn];
    __shared__ float sc3s[Kn], sc1[Kn], s_g[Kn];
    __shared__ float s_b[16], s_u[16], s_vk1[16];

    const int tid = threadIdx.x;
    const int bid = blockIdx.x;
    const int cshard = bid & 7;
    const int wid = tid >> 5, lane = tid & 31;
    int d_lo = bid * ROWS_PB; if (d_lo > Dn) d_lo = Dn;
    int d_hi = d_lo + ROWS_PB; if (d_hi > Dn) d_hi = Dn;
    const int nrows = d_hi - d_lo;
    unsigned gen = 0;

    {
        const float4* src = (const float4*)&g_C[(size_t)d_lo * Dn];
        float4* dst = (float4*)s_C;
        for (int i = tid; i < nrows * (Dn / 4); i += 256) dst[i] = src[i];
    }
    __syncthreads();

    for (int k = 0; k < Kn; ++k) {
        const int pin = k & 1, pout = pin ^ 1;

        // ---------------- P1 ----------------
        float s = 0.f, c1k1 = 0.f;
        if (k > 0) {
            s = rsqrtf(g_dn2[pin]);
            c1k1 = s * g_uv[pin];
            for (int j = tid; j < k - 1; j += 256) {
                sc3s[j] = g_c3[pin][j] * s;
                sc1[j]  = g_c1[pin][j];
            }
        }
        if (bid == 0) {
            for (int j = tid; j < Kn; j += 256) {
                g_c3[pout][j] = 0.f;
                g_c1[pout][j] = 0.f;
                g_g[j] = 0.f;
            }
            if (tid == 0) { g_dn2[pout] = 0.f; g_uv[pout] = 0.f; }
        }
        __syncthreads();

        if (k == 0) {
            for (int d = d_lo + tid; d < d_hi; d += 256)
                g_a[d] = g_Vt[d];
        } else {
            for (int dd = wid; dd < nrows; dd += 8) {
                int d = d_lo + dd;
                float u_d = s_u[dd];
                const float* wrow = &s_WT[dd * Kn];
                float sum1 = 0.f, sum2 = 0.f;
                #pragma unroll 4
                for (int j = lane; j < k - 1; j += 32) {
                    float wj = wrow[j];
                    sum1 += sc3s[j] * wj;
                    sum2 += sc1[j] * wj;
                }
                #pragma unroll
                for (int o = 16; o; o >>= 1) {
                    sum1 += __shfl_down_sync(~0u, sum1, o);
                    sum2 += __shfl_down_sync(~0u, sum2, o);
                }
                if (lane == 0) {
                    float vn_d = s * u_d;
                    float w_d = vn_d - sum1;
                    s_VnT[dd * Kn + (k - 1)] = vn_d;
                    g_VnT[(size_t)d * Kn + (k - 1)] = vn_d;
                    s_WT[dd * Kn + (k - 1)] = w_d;
                    g_a[d] = g_Vt[(size_t)k * Dn + d] - sum2 - c1k1 * w_d;
                }
            }
        }
        gbar(gen, cshard);

        // ---------------- P2: b = C a (SMEM rows), g_j partials ----------------
        for (int i = tid; i < Dn / 4; i += 256)
            ((float4*)s_a)[i] = ((const float4*)g_a)[i];
        __syncthreads();
        for (int dd = wid; dd < nrows; dd += 8) {
            const float4* crow = (const float4*)&s_C[dd * Dn];
            float sum = 0.f;
            #pragma unroll 4
            for (int t = lane; t < Dn / 4; t += 32) {
                float4 c4 = crow[t];
                float4 a4 = ((const float4*)s_a)[t];
                sum += c4.x * a4.x + c4.y * a4.y + c4.z * a4.z + c4.w * a4.w;
            }
            #pragma unroll
            for (int o = 16; o; o >>= 1) sum += __shfl_down_sync(~0u, sum, o);
            if (lane == 0) s_b[dd] = sum;
        }
        __syncthreads();
        if (tid < k && nrows > 0) {
            float accg = 0.f;
            #pragma unroll 7
            for (int dd = 0; dd < nrows; ++dd)
                accg += s_WT[dd * Kn + tid] * s_b[dd];
            atomicAdd(&g_g[tid], accg);
        }
        gbar(gen, cshard);

        // ---------------- P3: u update + next-step dots ----------------
        const float hh = 0.5f / g_d0[k];
        for (int j = tid; j < k; j += 256) s_g[j] = g_g[j];
        __syncthreads();
        for (int dd = wid; dd < nrows; dd += 8) {
            int d = d_lo + dd;
            const float* vrow = &s_VnT[dd * Kn];
            float sumg = 0.f;
            #pragma unroll 4
            for (int j = lane; j < k; j += 32) sumg += s_g[j] * vrow[j];
            #pragma unroll
            for (int o = 16; o; o >>= 1) sumg += __shfl_down_sync(~0u, sumg, o);
            if (lane == 0) {
                float u_d = 0.5f * g_Vt[(size_t)k * Dn + d] + hh * (s_b[dd] - sumg);
                s_u[dd] = u_d;
                s_vk1[dd] = (k + 1 < Kn) ? g_Vt[(size_t)(k + 1) * Dn + d] : 0.f;
            }
        }
        __syncthreads();
        if (tid < k && nrows > 0) {
            float a3 = 0.f, a1 = 0.f;
            #pragma unroll 7
            for (int dd = 0; dd < nrows; ++dd) {
                float vv = s_VnT[dd * Kn + tid];
                a3 += vv * s_u[dd];
                a1 += vv * s_vk1[dd];
            }
            atomicAdd(&g_c3[pout][tid], a3);
            atomicAdd(&g_c1[pout][tid], a1);
        }
        if (tid == 0 && nrows > 0) {
            float d2 = 0.f, uvv = 0.f;
            #pragma unroll 7
            for (int dd = 0; dd < nrows; ++dd) {
                d2  += s_u[dd] * s_u[dd];
                uvv += s_u[dd] * s_vk1[dd];
            }
            atomicAdd(&g_dn2[pout], d2);
            atomicAdd(&g_uv[pout], uvv);
        }
        gbar(gen, cshard);
    }

    // epilogue: write vn_{K-1}
    {
        const int plast = ((Kn - 1) & 1) ^ 1;
        float sfin = rsqrtf(g_dn2[plast]);
        for (int dd = tid; dd < nrows; dd += 256)
            g_VnT[(size_t)(d_lo + dd) * Kn + (Kn - 1)] = sfin * s_u[dd];
    }

    // reset barrier state for the next graph replay (globally-last block)
    __syncthreads();
    if (tid == 0) {
        __threadfence();
        if (atomicAdd(&g_done, 1u) == (unsigned)(gridDim.x - 1)) {
            #pragma unroll
            for (int c = 0; c < 8; ++c) g_cnt[c * 256] = 0u;
            g_done = 0u;
            __threadfence();
        }
    }
}

// ---------------- out = x @ VnT (double-buffered, f32x2) ----------------
__global__ void __launch_bounds__(256) gemmOut_kernel(const float* __restrict__ x,
                                                      float* __restrict__ out) {
    __shared__ __align__(16) float As[2][16][132];
    __shared__ __align__(16) float Bs[2][16][64];

    const int br = blockIdx.x >> 2;
    const int bc = blockIdx.x & 3;
    const int tid = threadIdx.x;
    const int ty = tid >> 4, tx = tid & 15;
    const int n0 = br * 128;

    ull acc2[8][2];
    const ull z = splat2(0.f);
    #pragma unroll
    for (int p = 0; p < 8; ++p) { acc2[p][0] = z; acc2[p][1] = z; }

    const int ra0 = tid >> 2, ca0 = tid & 3;
    const int ra1 = (tid + 256) >> 2, ca1 = tid & 3;
    const int rb = tid >> 4, cb = tid & 15;

    float4 va0, va1, vb;
    auto stage = [&](int b) {
        As[b][ca0 * 4 + 0][ra0] = va0.x;
        As[b][ca0 * 4 + 1][ra0] = va0.y;
        As[b][ca0 * 4 + 2][ra0] = va0.z;
        As[b][ca0 * 4 + 3][ra0] = va0.w;
        As[b][ca1 * 4 + 0][ra1] = va1.x;
        As[b][ca1 * 4 + 1][ra1] = va1.y;
        As[b][ca1 * 4 + 2][ra1] = va1.z;
        As[b][ca1 * 4 + 3][ra1] = va1.w;
        ((float4*)&Bs[b][rb][0])[cb] = vb;
    };

    va0 = *(const float4*)(x + (size_t)(n0 + ra0) * Dn + ca0 * 4);
    va1 = *(const float4*)(x + (size_t)(n0 + ra1) * Dn + ca1 * 4);
    vb  = *(const float4*)(&g_VnT[(size_t)rb * Kn + bc * 64 + cb * 4]);
    stage(0);

    int buf = 0;
    for (int dchunk = 0; dchunk < Dn; dchunk += 16) {
        __syncthreads();
        const bool more = (dchunk + 16 < Dn);
        if (more) {
            int dn = dchunk + 16;
            va0 = *(const float4*)(x + (size_t)(n0 + ra0) * Dn + dn + ca0 * 4);
            va1 = *(const float4*)(x + (size_t)(n0 + ra1) * Dn + dn + ca1 * 4);
            vb  = *(const float4*)(&g_VnT[(size_t)(dn + rb) * Kn + bc * 64 + cb * 4]);
        }
        #pragma unroll
        for (int kk = 0; kk < 16; ++kk) {
            float a8[8];
            *(float4*)&a8[0] = *(const float4*)&As[buf][kk][ty * 8];
            *(float4*)&a8[4] = *(const float4*)&As[buf][kk][ty * 8 + 4];
            const ull* bp = (const ull*)&Bs[buf][kk][tx * 4];
            ull b2[2] = { bp[0], bp[1] };
            #pragma unroll
            for (int p = 0; p < 8; ++p) {
                ull ap = splat2(a8[p]);
                fma2(acc2[p][0], ap, b2[0]);
                fma2(acc2[p][1], ap, b2[1]);
            }
        }
        if (more) stage(buf ^ 1);
        buf ^= 1;
    }

    #pragma unroll
    for (int p = 0; p < 8; ++p) {
        float2 v0 = *(float2*)&acc2[p][0];
        float2 v1 = *(float2*)&acc2[p][1];
        *(float4*)(out + (size_t)(n0 + ty * 8 + p) * Kn + bc * 64 + tx * 4) =
            make_float4(v0.x, v0.y, v1.x, v1.y);
    }
}

// ---------------- launch ----------------
extern "C" void kernel_launch(void* const* d_in, const int* in_sizes, int n_in,
                              void* d_out, int out_size) {
    const float* x  = (const float*)d_in[0];
    const float* V0 = (const float*)d_in[1];
    if (n_in >= 2 && in_sizes[0] == Dn * Kn && in_sizes[1] == Nn * Dn) {
        const float* t = x; x = V0; V0 = t;
    }
    float* out = (float*)d_out;

    static int smem_set = 0;
    const int dyn_smem = (ROWS_PB * Dn + 2 * ROWS_PB * Kn) * (int)sizeof(float); // 143360
    if (!smem_set) {
        cudaFuncSetAttribute(solve_kernel,
                             cudaFuncAttributeMaxDynamicSharedMemorySize, dyn_smem);
        smem_set = 1;
    }

    splitx_kernel<<<2048, 256>>>(x);
    prep_kernel<<<Kn, 256>>>(V0);
    gemmC_tc_kernel<<<136, 256>>>();
    solve_kernel<<<NBLK, 256, dyn_smem>>>();
    gemmOut_kernel<<<256, 256>>>(x, out);
}

// round 14
// speedup vs baseline: 1.4887x; 1.4887x over previous
#include <cuda_runtime.h>
#include <cuda_bf16.h>
#include <math.h>

#define Nn 8192
#define Dn 2048
#define Kn 256
#define NBLK 148
#define ROWS_PB 14            // 148 * 14 = 2072 >= 2048

typedef unsigned long long ull;
typedef unsigned int u32;
typedef unsigned short u16;

// ---------------- f32x2 packed FMA helpers (Blackwell FFMA2) ----------------
__device__ __forceinline__ ull splat2(float s) {
    ull d;
    asm("mov.b64 %0, {%1, %1};" : "=l"(d) : "r"(__float_as_uint(s)));
    return d;
}
__device__ __forceinline__ void fma2(ull& d, ull a, ull b) {
    asm("fma.rn.f32x2 %0, %1, %2, %0;" : "+l"(d) : "l"(a), "l"(b));
}

// ---------------- device scratch (static: no allocation allowed) ----------------
__device__ float g_C[(size_t)Dn * Dn];          // 16 MB  C = x^T x (L2-resident)
__device__ __nv_bfloat16 g_xh[(size_t)Nn * Dn]; // 32 MB hi split
__device__ __nv_bfloat16 g_xl[(size_t)Nn * Dn]; // 32 MB lo split
__device__ float g_Vt[(size_t)Kn * Dn];
__device__ float g_VnT[(size_t)Dn * Kn];
__device__ float g_a[Dn];
__device__ float g_c1[2][Kn];
__device__ float g_c3[2][Kn];
__device__ float g_g[Kn];
__device__ float g_d0[Kn];
__device__ float g_dn2[2];
__device__ float g_uv[2];
__device__ __align__(128) unsigned g_barcnt;   // single counter (R3 — measured best)
__device__ __align__(128) unsigned g_done;

// ---------------- grid barrier: R3 single counter + polite poll ---------------
// Six designs tested; R3's single red.release counter is the floor. Residual
// cost attributed to poll-read interference on the hot line. Fix: poll with
// RELAXED loads + __nanosleep backoff; issue ONE acquire load after the
// condition holds to establish ordering.
__device__ __forceinline__ void gbar(unsigned& gen) {
    gen += gridDim.x;
    __syncthreads();
    if (threadIdx.x == 0) {
        asm volatile("red.release.gpu.global.add.u32 [%0], 1;"
                     :: "l"(&g_barcnt) : "memory");
        unsigned v;
        asm volatile("ld.relaxed.gpu.global.u32 %0, [%1];"
                     : "=r"(v) : "l"(&g_barcnt) : "memory");
        while ((int)(v - gen) < 0) {
            __nanosleep(64);
            asm volatile("ld.relaxed.gpu.global.u32 %0, [%1];"
                         : "=r"(v) : "l"(&g_barcnt) : "memory");
        }
        // ordering: one acquire load now that the barrier has opened
        asm volatile("ld.acquire.gpu.global.u32 %0, [%1];"
                     : "=r"(v) : "l"(&g_barcnt) : "memory");
    }
    __syncthreads();
}

// ---------------- split x into bf16 hi + lo ----------------
__global__ void __launch_bounds__(256) splitx_kernel(const float* __restrict__ x) {
    const int stride = gridDim.x * 256;
    for (int i = blockIdx.x * 256 + threadIdx.x; i < Nn * Dn / 4; i += stride) {
        float4 v = ((const float4*)x)[i];
        __nv_bfloat16 h0 = __float2bfloat16(v.x);
        __nv_bfloat16 h1 = __float2bfloat16(v.y);
        __nv_bfloat16 h2 = __float2bfloat16(v.z);
        __nv_bfloat16 h3 = __float2bfloat16(v.w);
        __nv_bfloat16 l0 = __float2bfloat16(v.x - __bfloat162float(h0));
        __nv_bfloat16 l1 = __float2bfloat16(v.y - __bfloat162float(h1));
        __nv_bfloat16 l2 = __float2bfloat16(v.z - __bfloat162float(h2));
        __nv_bfloat16 l3 = __float2bfloat16(v.w - __bfloat162float(h3));
        ushort4 hh, ll;
        hh.x = *(u16*)&h0; hh.y = *(u16*)&h1; hh.z = *(u16*)&h2; hh.w = *(u16*)&h3;
        ll.x = *(u16*)&l0; ll.y = *(u16*)&l1; ll.z = *(u16*)&l2; ll.w = *(u16*)&l3;
        ((ushort4*)g_xh)[i] = hh;
        ((ushort4*)g_xl)[i] = ll;
    }
}

// ---------------- prep: transpose V0 -> Vt, per-column norms d0 ----------------
__global__ void __launch_bounds__(256) prep_kernel(const float* __restrict__ V0) {
    __shared__ float sb[8];
    int k = blockIdx.x;
    float s = 0.f;
    for (int d = threadIdx.x; d < Dn; d += 256) {
        float v = V0[(size_t)d * Kn + k];
        g_Vt[(size_t)k * Dn + d] = v;
        s += v * v;
    }
    #pragma unroll
    for (int o = 16; o; o >>= 1) s += __shfl_down_sync(~0u, s, o);
    if ((threadIdx.x & 31) == 0) sb[threadIdx.x >> 5] = s;
    __syncthreads();
    if (threadIdx.x == 0) {
        float t = 0.f;
        #pragma unroll
        for (int w = 0; w < 8; ++w) t += sb[w];
        g_d0[k] = sqrtf(t);
    }
}

// ---------------- tensor-core helpers ----------------
__device__ __forceinline__ void ldsm4t(u32& r0, u32& r1, u32& r2, u32& r3, u32 addr) {
    asm volatile("ldmatrix.sync.aligned.m8n8.x4.trans.shared.b16 {%0,%1,%2,%3}, [%4];"
                 : "=r"(r0), "=r"(r1), "=r"(r2), "=r"(r3) : "r"(addr));
}
__device__ __forceinline__ void mma16816(float* c, const u32* a, const u32* b) {
    asm volatile(
        "mma.sync.aligned.m16n8k16.row.col.f32.bf16.bf16.f32 "
        "{%0,%1,%2,%3}, {%4,%5,%6,%7}, {%8,%9}, {%0,%1,%2,%3};"
        : "+f"(c[0]), "+f"(c[1]), "+f"(c[2]), "+f"(c[3])
        : "r"(a[0]), "r"(a[1]), "r"(a[2]), "r"(a[3]), "r"(b[0]), "r"(b[1]));
}

// ---------------- C = xh^T xh + xh^T xl + xl^T xh (tensor cores) ---------------
__global__ void __launch_bounds__(256) gemmC_tc_kernel() {
    __shared__ __align__(16) char smt[2][4][16 * 256];

    int rem = blockIdx.x, bi = 0, width = 16;
    while (rem >= width) { rem -= width; ++bi; --width; }
    int bj = bi + rem;

    const int tid = threadIdx.x;
    const int warp = tid >> 5, lane = tid & 31;
    const int wm = warp >> 2, wn = warp & 3;

    float acc[4][4][4];
    #pragma unroll
    for (int i = 0; i < 4; ++i)
        #pragma unroll
        for (int j = 0; j < 4; ++j)
            #pragma unroll
            for (int r = 0; r < 4; ++r) acc[i][j][r] = 0.f;

    const int ln = tid >> 4;
    const int lc = tid & 15;
    const int sw_off = ln * 256 + ((lc ^ (ln & 7)) << 4);
    const size_t gA = (size_t)ln * Dn + bi * 128 + lc * 8;
    const size_t gB = (size_t)ln * Dn + bj * 128 + lc * 8;

    const int q = lane >> 3, r8 = lane & 7;
    int a_colh[4], a_row[4];
    #pragma unroll
    for (int i = 0; i < 4; ++i) {
        int m_off = (q & 1) << 3, k_off = (q >> 1) << 3;
        a_colh[i] = wm * 64 + (i << 4) + m_off;
        a_row[i]  = k_off + r8;
    }
    int b_colh[2], b_row[2];
    #pragma unroll
    for (int p = 0; p < 2; ++p) {
        int n_off = (p << 4) + ((q >> 1) << 3);
        int k_off = (q & 1) << 3;
        b_colh[p] = wn * 32 + n_off;
        b_row[p]  = k_off + r8;
    }
    u32 aoff[4], boff[2];
    #pragma unroll
    for (int i = 0; i < 4; ++i)
        aoff[i] = a_row[i] * 256 + ((((u32)a_colh[i] >> 3) ^ (a_row[i] & 7)) << 4);
    #pragma unroll
    for (int p = 0; p < 2; ++p)
        boff[p] = b_row[p] * 256 + ((((u32)b_colh[p] >> 3) ^ (b_row[p] & 7)) << 4);

    const u32 smem_base = (u32)__cvta_generic_to_shared(&smt[0][0][0]);

    uint4 pf0, pf1, pf2, pf3;
    pf0 = *(const uint4*)(g_xh + gA);
    pf1 = *(const uint4*)(g_xl + gA);
    pf2 = *(const uint4*)(g_xh + gB);
    pf3 = *(const uint4*)(g_xl + gB);
    *(uint4*)(smt[0][0] + sw_off) = pf0;
    *(uint4*)(smt[0][1] + sw_off) = pf1;
    *(uint4*)(smt[0][2] + sw_off) = pf2;
    *(uint4*)(smt[0][3] + sw_off) = pf3;
    __syncthreads();

    int buf = 0;
    for (int n0 = 0; n0 < Nn; n0 += 16) {
        const bool more = (n0 + 16 < Nn);
        if (more) {
            size_t adv = (size_t)(n0 + 16) * Dn;
            pf0 = *(const uint4*)(g_xh + gA + adv);
            pf1 = *(const uint4*)(g_xl + gA + adv);
            pf2 = *(const uint4*)(g_xh + gB + adv);
            pf3 = *(const uint4*)(g_xl + gB + adv);
        }
        const u32 tb = smem_base + buf * (4 * 4096);
        u32 Ah[4][4], Al[4][4], Bh[4][2], Bl[4][2];
        #pragma unroll
        for (int i = 0; i < 4; ++i) {
            ldsm4t(Ah[i][0], Ah[i][1], Ah[i][2], Ah[i][3], tb + 0 * 4096 + aoff[i]);
            ldsm4t(Al[i][0], Al[i][1], Al[i][2], Al[i][3], tb + 1 * 4096 + aoff[i]);
        }
        #pragma unroll
        for (int p = 0; p < 2; ++p) {
            ldsm4t(Bh[2 * p][0], Bh[2 * p][1], Bh[2 * p + 1][0], Bh[2 * p + 1][1],
                   tb + 2 * 4096 + boff[p]);
            ldsm4t(Bl[2 * p][0], Bl[2 * p][1], Bl[2 * p + 1][0], Bl[2 * p + 1][1],
                   tb + 3 * 4096 + boff[p]);
        }
        #pragma unroll
        for (int i = 0; i < 4; ++i)
            #pragma unroll
            for (int j = 0; j < 4; ++j) {
                mma16816(acc[i][j], Ah[i], Bh[j]);
                mma16816(acc[i][j], Ah[i], Bl[j]);
                mma16816(acc[i][j], Al[i], Bh[j]);
            }
        if (more) {
            int nb = buf ^ 1;
            *(uint4*)(smt[nb][0] + sw_off) = pf0;
            *(uint4*)(smt[nb][1] + sw_off) = pf1;
            *(uint4*)(smt[nb][2] + sw_off) = pf2;
            *(uint4*)(smt[nb][3] + sw_off) = pf3;
        }
        __syncthreads();
        buf ^= 1;
    }

    const int row0 = lane >> 2, col0 = (lane & 3) * 2;
    #pragma unroll
    for (int i = 0; i < 4; ++i) {
        #pragma unroll
        for (int j = 0; j < 4; ++j) {
            int gi = bi * 128 + wm * 64 + i * 16 + row0;
            int gj = bj * 128 + wn * 32 + j * 8 + col0;
            *(float2*)(g_C + (size_t)gi * Dn + gj) =
                make_float2(acc[i][j][0], acc[i][j][1]);
            *(float2*)(g_C + (size_t)(gi + 8) * Dn + gj) =
                make_float2(acc[i][j][2], acc[i][j][3]);
            if (bi != bj) {
                g_C[(size_t)gj * Dn + gi]           = acc[i][j][0];
                g_C[(size_t)(gj + 1) * Dn + gi]     = acc[i][j][1];
                g_C[(size_t)gj * Dn + gi + 8]       = acc[i][j][2];
                g_C[(size_t)(gj + 1) * Dn + gi + 8] = acc[i][j][3];
            }
        }
    }
}

// ---------------- persistent sequential CCIPCA solve (R3 form) ----------------
__global__ void __launch_bounds__(256) solve_kernel() {
    extern __shared__ __align__(16) float s_dyn[];
    float* s_C   = s_dyn;
    float* s_WT  = s_dyn + ROWS_PB * Dn;
    float* s_VnT = s_dyn + ROWS_PB * Dn + ROWS_PB * Kn;
    __shared__ __align__(16) float s_a[Dn];
    __shared__ float sc3s[Kn], sc1[Kn], s_g[Kn];
    __shared__ float s_b[16], s_u[16], s_vk1[16];

    const int tid = threadIdx.x;
    const int bid = blockIdx.x;
    const int wid = tid >> 5, lane = tid & 31;
    int d_lo = bid * ROWS_PB; if (d_lo > Dn) d_lo = Dn;
    int d_hi = d_lo + ROWS_PB; if (d_hi > Dn) d_hi = Dn;
    const int nrows = d_hi - d_lo;
    unsigned gen = 0;

    {
        const float4* src = (const float4*)&g_C[(size_t)d_lo * Dn];
        float4* dst = (float4*)s_C;
        for (int i = tid; i < nrows * (Dn / 4); i += 256) dst[i] = src[i];
    }
    __syncthreads();

    for (int k = 0; k < Kn; ++k) {
        const int pin = k & 1, pout = pin ^ 1;

        // ---------------- P1 ----------------
        float s = 0.f, c1k1 = 0.f;
        if (k > 0) {
            s = rsqrtf(g_dn2[pin]);
            c1k1 = s * g_uv[pin];
            for (int j = tid; j < k - 1; j += 256) {
                sc3s[j] = g_c3[pin][j] * s;
                sc1[j]  = g_c1[pin][j];
            }
        }
        if (bid == NBLK - 1) {   // block 147 owns 0 rows: zeroing duty
            for (int j = tid; j < Kn; j += 256) {
                g_c3[pout][j] = 0.f;
                g_c1[pout][j] = 0.f;
                g_g[j] = 0.f;
            }
            if (tid == 0) { g_dn2[pout] = 0.f; g_uv[pout] = 0.f; }
        }
        __syncthreads();

        if (k == 0) {
            for (int d = d_lo + tid; d < d_hi; d += 256)
                g_a[d] = g_Vt[d];
        } else {
            for (int dd = wid; dd < nrows; dd += 8) {
                int d = d_lo + dd;
                float u_d = s_u[dd];
                const float* wrow = &s_WT[dd * Kn];
                float sum1 = 0.f, sum2 = 0.f;
                #pragma unroll 4
                for (int j = lane; j < k - 1; j += 32) {
                    float wj = wrow[j];
                    sum1 += sc3s[j] * wj;
                    sum2 += sc1[j] * wj;
                }
                #pragma unroll
                for (int o = 16; o; o >>= 1) {
                    sum1 += __shfl_down_sync(~0u, sum1, o);
                    sum2 += __shfl_down_sync(~0u, sum2, o);
                }
                if (lane == 0) {
                    float vn_d = s * u_d;
                    float w_d = vn_d - sum1;
                    s_VnT[dd * Kn + (k - 1)] = vn_d;
                    g_VnT[(size_t)d * Kn + (k - 1)] = vn_d;
                    s_WT[dd * Kn + (k - 1)] = w_d;
                    g_a[d] = g_Vt[(size_t)k * Dn + d] - sum2 - c1k1 * w_d;
                }
            }
        }
        gbar(gen);

        // ---------------- P2: b = C a (SMEM rows), g_j partials ----------------
        for (int i = tid; i < Dn / 4; i += 256)
            ((float4*)s_a)[i] = ((const float4*)g_a)[i];
        __syncthreads();
        for (int dd = wid; dd < nrows; dd += 8) {
            const float4* crow = (const float4*)&s_C[dd * Dn];
            float sum = 0.f;
            #pragma unroll 4
            for (int t = lane; t < Dn / 4; t += 32) {
                float4 c4 = crow[t];
                float4 a4 = ((const float4*)s_a)[t];
                sum += c4.x * a4.x + c4.y * a4.y + c4.z * a4.z + c4.w * a4.w;
            }
            #pragma unroll
            for (int o = 16; o; o >>= 1) sum += __shfl_down_sync(~0u, sum, o);
            if (lane == 0) s_b[dd] = sum;
        }
        __syncthreads();
        if (tid < k && nrows > 0) {
            float accg = 0.f;
            #pragma unroll 7
            for (int dd = 0; dd < nrows; ++dd)
                accg += s_WT[dd * Kn + tid] * s_b[dd];
            atomicAdd(&g_g[tid], accg);
        }
        gbar(gen);

        // ---------------- P3: u update + next-step dots ----------------
        const float hh = 0.5f / g_d0[k];
        for (int j = tid; j < k; j += 256) s_g[j] = g_g[j];
        __syncthreads();
        for (int dd = wid; dd < nrows; dd += 8) {
            int d = d_lo + dd;
            const float* vrow = &s_VnT[dd * Kn];
            float sumg = 0.f;
            #pragma unroll 4
            for (int j = lane; j < k; j += 32) sumg += s_g[j] * vrow[j];
            #pragma unroll
            for (int o = 16; o; o >>= 1) sumg += __shfl_down_sync(~0u, sumg, o);
            if (lane == 0) {
                float u_d = 0.5f * g_Vt[(size_t)k * Dn + d] + hh * (s_b[dd] - sumg);
                s_u[dd] = u_d;
                s_vk1[dd] = (k + 1 < Kn) ? g_Vt[(size_t)(k + 1) * Dn + d] : 0.f;
            }
        }
        __syncthreads();
        if (tid < k && nrows > 0) {
            float a3 = 0.f, a1 = 0.f;
            #pragma unroll 7
            for (int dd = 0; dd < nrows; ++dd) {
                float vv = s_VnT[dd * Kn + tid];
                a3 += vv * s_u[dd];
                a1 += vv * s_vk1[dd];
            }
            atomicAdd(&g_c3[pout][tid], a3);
            atomicAdd(&g_c1[pout][tid], a1);
        }
        if (tid == 0 && nrows > 0) {
            float d2 = 0.f, uvv = 0.f;
            #pragma unroll 7
            for (int dd = 0; dd < nrows; ++dd) {
                d2  += s_u[dd] * s_u[dd];
                uvv += s_u[dd] * s_vk1[dd];
            }
            atomicAdd(&g_dn2[pout], d2);
            atomicAdd(&g_uv[pout], uvv);
        }
        gbar(gen);
    }

    // epilogue: write vn_{K-1}
    {
        const int plast = ((Kn - 1) & 1) ^ 1;
        float sfin = rsqrtf(g_dn2[plast]);
        for (int dd = tid; dd < nrows; dd += 256)
            g_VnT[(size_t)(d_lo + dd) * Kn + (Kn - 1)] = sfin * s_u[dd];
    }

    // reset barrier state for the next graph replay (globally-last block)
    __syncthreads();
    if (tid == 0) {
        __threadfence();
        if (atomicAdd(&g_done, 1u) == (unsigned)(gridDim.x - 1)) {
            g_done = 0u;
            g_barcnt = 0u;
            __threadfence();
        }
    }
}

// ---------------- out = x @ VnT (double-buffered, f32x2) ----------------
__global__ void __launch_bounds__(256) gemmOut_kernel(const float* __restrict__ x,
                                                      float* __restrict__ out) {
    __shared__ __align__(16) float As[2][16][132];
    __shared__ __align__(16) float Bs[2][16][64];

    const int br = blockIdx.x >> 2;
    const int bc = blockIdx.x & 3;
    const int tid = threadIdx.x;
    const int ty = tid >> 4, tx = tid & 15;
    const int n0 = br * 128;

    ull acc2[8][2];
    const ull z = splat2(0.f);
    #pragma unroll
    for (int p = 0; p < 8; ++p) { acc2[p][0] = z; acc2[p][1] = z; }

    const int ra0 = tid >> 2, ca0 = tid & 3;
    const int ra1 = (tid + 256) >> 2, ca1 = tid & 3;
    const int rb = tid >> 4, cb = tid & 15;

    float4 va0, va1, vb;
    auto stage = [&](int b) {
        As[b][ca0 * 4 + 0][ra0] = va0.x;
        As[b][ca0 * 4 + 1][ra0] = va0.y;
        As[b][ca0 * 4 + 2][ra0] = va0.z;
        As[b][ca0 * 4 + 3][ra0] = va0.w;
        As[b][ca1 * 4 + 0][ra1] = va1.x;
        As[b][ca1 * 4 + 1][ra1] = va1.y;
        As[b][ca1 * 4 + 2][ra1] = va1.z;
        As[b][ca1 * 4 + 3][ra1] = va1.w;
        ((float4*)&Bs[b][rb][0])[cb] = vb;
    };

    va0 = *(const float4*)(x + (size_t)(n0 + ra0) * Dn + ca0 * 4);
    va1 = *(const float4*)(x + (size_t)(n0 + ra1) * Dn + ca1 * 4);
    vb  = *(const float4*)(&g_VnT[(size_t)rb * Kn + bc * 64 + cb * 4]);
    stage(0);

    int buf = 0;
    for (int dchunk = 0; dchunk < Dn; dchunk += 16) {
        __syncthreads();
        const bool more = (dchunk + 16 < Dn);
        if (more) {
            int dn = dchunk + 16;
            va0 = *(const float4*)(x + (size_t)(n0 + ra0) * Dn + dn + ca0 * 4);
            va1 = *(const float4*)(x + (size_t)(n0 + ra1) * Dn + dn + ca1 * 4);
            vb  = *(const float4*)(&g_VnT[(size_t)(dn + rb) * Kn + bc * 64 + cb * 4]);
        }
        #pragma unroll
        for (int kk = 0; kk < 16; ++kk) {
            float a8[8];
            *(float4*)&a8[0] = *(const float4*)&As[buf][kk][ty * 8];
            *(float4*)&a8[4] = *(const float4*)&As[buf][kk][ty * 8 + 4];
            const ull* bp = (const ull*)&Bs[buf][kk][tx * 4];
            ull b2[2] = { bp[0], bp[1] };
            #pragma unroll
            for (int p = 0; p < 8; ++p) {
                ull ap = splat2(a8[p]);
                fma2(acc2[p][0], ap, b2[0]);
                fma2(acc2[p][1], ap, b2[1]);
            }
        }
        if (more) stage(buf ^ 1);
        buf ^= 1;
    }

    #pragma unroll
    for (int p = 0; p < 8; ++p) {
        float2 v0 = *(float2*)&acc2[p][0];
        float2 v1 = *(float2*)&acc2[p][1];
        *(float4*)(out + (size_t)(n0 + ty * 8 + p) * Kn + bc * 64 + tx * 4) =
            make_float4(v0.x, v0.y, v1.x, v1.y);
    }
}

// ---------------- launch ----------------
extern "C" void kernel_launch(void* const* d_in, const int* in_sizes, int n_in,
                              void* d_out, int out_size) {
    const float* x  = (const float*)d_in[0];
    const float* V0 = (const float*)d_in[1];
    if (n_in >= 2 && in_sizes[0] == Dn * Kn && in_sizes[1] == Nn * Dn) {
        const float* t = x; x = V0; V0 = t;
    }
    float* out = (float*)d_out;

    static int smem_set = 0;
    const int dyn_smem = (ROWS_PB * Dn + 2 * ROWS_PB * Kn) * (int)sizeof(float); // 143360
    if (!smem_set) {
        cudaFuncSetAttribute(solve_kernel,
                             cudaFuncAttributeMaxDynamicSharedMemorySize, dyn_smem);
        smem_set = 1;
    }

    splitx_kernel<<<2048, 256>>>(x);
    prep_kernel<<<Kn, 256>>>(V0);
    gemmC_tc_kernel<<<136, 256>>>();
    solve_kernel<<<NBLK, 256, dyn_smem>>>();
    gemmOut_kernel<<<256, 256>>>(x, out);
}

// round 15
// speedup vs baseline: 1.5688x; 1.0538x over previous
#include <cuda_runtime.h>
#include <cuda_bf16.h>
#include <math.h>

#define Nn 8192
#define Dn 2048
#define Kn 256
#define NBLK 148
#define ROWS_PB 14            // 148 * 14 = 2072 >= 2048

typedef unsigned long long ull;
typedef unsigned int u32;
typedef unsigned short u16;

// ---------------- device scratch (static: no allocation allowed) ----------------
__device__ float g_C[(size_t)Dn * Dn];          // 16 MB  C = x^T x (L2-resident)
__device__ __nv_bfloat16 g_xh[(size_t)Nn * Dn]; // 32 MB hi split of x
__device__ __nv_bfloat16 g_xl[(size_t)Nn * Dn]; // 32 MB lo split of x
__device__ __nv_bfloat16 g_Vh[(size_t)Dn * Kn]; // 1 MB  hi split of Vn
__device__ __nv_bfloat16 g_Vl[(size_t)Dn * Kn]; // 1 MB  lo split of Vn
__device__ float g_Vt[(size_t)Kn * Dn];
__device__ float g_a[Dn];
__device__ float g_c1[2][Kn];
__device__ float g_c3[2][Kn];
__device__ float g_g[Kn];
__device__ float g_d0[Kn];
__device__ float g_dn2[2];
__device__ float g_uv[2];
__device__ __align__(128) unsigned g_barcnt;   // single counter (measured best)
__device__ __align__(128) unsigned g_done;

// ---------------- grid barrier: R3 single counter + polite poll (R13-best) ----
__device__ __forceinline__ void gbar(unsigned& gen) {
    gen += gridDim.x;
    __syncthreads();
    if (threadIdx.x == 0) {
        asm volatile("red.release.gpu.global.add.u32 [%0], 1;"
                     :: "l"(&g_barcnt) : "memory");
        unsigned v;
        asm volatile("ld.relaxed.gpu.global.u32 %0, [%1];"
                     : "=r"(v) : "l"(&g_barcnt) : "memory");
        while ((int)(v - gen) < 0) {
            __nanosleep(64);
            asm volatile("ld.relaxed.gpu.global.u32 %0, [%1];"
                         : "=r"(v) : "l"(&g_barcnt) : "memory");
        }
        asm volatile("ld.acquire.gpu.global.u32 %0, [%1];"
                     : "=r"(v) : "l"(&g_barcnt) : "memory");
    }
    __syncthreads();
}

// ---------------- cp.async helper ----------------
__device__ __forceinline__ void cpasync16(u32 saddr, const void* gaddr) {
    asm volatile("cp.async.cg.shared.global [%0], [%1], 16;"
                 :: "r"(saddr), "l"(gaddr) : "memory");
}

// ---------------- split x into bf16 hi + lo ----------------
__global__ void __launch_bounds__(256) splitx_kernel(const float* __restrict__ x) {
    const int stride = gridDim.x * 256;
    for (int i = blockIdx.x * 256 + threadIdx.x; i < Nn * Dn / 4; i += stride) {
        float4 v = ((const float4*)x)[i];
        __nv_bfloat16 h0 = __float2bfloat16(v.x);
        __nv_bfloat16 h1 = __float2bfloat16(v.y);
        __nv_bfloat16 h2 = __float2bfloat16(v.z);
        __nv_bfloat16 h3 = __float2bfloat16(v.w);
        __nv_bfloat16 l0 = __float2bfloat16(v.x - __bfloat162float(h0));
        __nv_bfloat16 l1 = __float2bfloat16(v.y - __bfloat162float(h1));
        __nv_bfloat16 l2 = __float2bfloat16(v.z - __bfloat162float(h2));
        __nv_bfloat16 l3 = __float2bfloat16(v.w - __bfloat162float(h3));
        ushort4 hh, ll;
        hh.x = *(u16*)&h0; hh.y = *(u16*)&h1; hh.z = *(u16*)&h2; hh.w = *(u16*)&h3;
        ll.x = *(u16*)&l0; ll.y = *(u16*)&l1; ll.z = *(u16*)&l2; ll.w = *(u16*)&l3;
        ((ushort4*)g_xh)[i] = hh;
        ((ushort4*)g_xl)[i] = ll;
    }
}

// ---------------- prep: transpose V0 -> Vt, per-column norms d0 ----------------
__global__ void __launch_bounds__(256) prep_kernel(const float* __restrict__ V0) {
    __shared__ float sb[8];
    int k = blockIdx.x;
    float s = 0.f;
    for (int d = threadIdx.x; d < Dn; d += 256) {
        float v = V0[(size_t)d * Kn + k];
        g_Vt[(size_t)k * Dn + d] = v;
        s += v * v;
    }
    #pragma unroll
    for (int o = 16; o; o >>= 1) s += __shfl_down_sync(~0u, s, o);
    if ((threadIdx.x & 31) == 0) sb[threadIdx.x >> 5] = s;
    __syncthreads();
    if (threadIdx.x == 0) {
        float t = 0.f;
        #pragma unroll
        for (int w = 0; w < 8; ++w) t += sb[w];
        g_d0[k] = sqrtf(t);
    }
}

// ---------------- tensor-core helpers ----------------
__device__ __forceinline__ void ldsm4t(u32& r0, u32& r1, u32& r2, u32& r3, u32 addr) {
    asm volatile("ldmatrix.sync.aligned.m8n8.x4.trans.shared.b16 {%0,%1,%2,%3}, [%4];"
                 : "=r"(r0), "=r"(r1), "=r"(r2), "=r"(r3) : "r"(addr));
}
__device__ __forceinline__ void ldsm4(u32& r0, u32& r1, u32& r2, u32& r3, u32 addr) {
    asm volatile("ldmatrix.sync.aligned.m8n8.x4.shared.b16 {%0,%1,%2,%3}, [%4];"
                 : "=r"(r0), "=r"(r1), "=r"(r2), "=r"(r3) : "r"(addr));
}
__device__ __forceinline__ void mma16816(float* c, const u32* a, const u32* b) {
    asm volatile(
        "mma.sync.aligned.m16n8k16.row.col.f32.bf16.bf16.f32 "
        "{%0,%1,%2,%3}, {%4,%5,%6,%7}, {%8,%9}, {%0,%1,%2,%3};"
        : "+f"(c[0]), "+f"(c[1]), "+f"(c[2]), "+f"(c[3])
        : "r"(a[0]), "r"(a[1]), "r"(a[2]), "r"(a[3]), "r"(b[0]), "r"(b[1]));
}

// ---------------- C = xh^T xh + xh^T xl + xl^T xh (TC, 3-stage cp.async) ------
__global__ void __launch_bounds__(256) gemmC_tc_kernel() {
    __shared__ __align__(16) char smt[3][4][16 * 256];   // 48 KB

    int rem = blockIdx.x, bi = 0, width = 16;
    while (rem >= width) { rem -= width; ++bi; --width; }
    int bj = bi + rem;

    const int tid = threadIdx.x;
    const int warp = tid >> 5, lane = tid & 31;
    const int wm = warp >> 2, wn = warp & 3;

    float acc[4][4][4];
    #pragma unroll
    for (int i = 0; i < 4; ++i)
        #pragma unroll
        for (int j = 0; j < 4; ++j)
            #pragma unroll
            for (int r = 0; r < 4; ++r) acc[i][j][r] = 0.f;

    const int ln = tid >> 4;
    const int lc = tid & 15;
    const u32 sw_off = ln * 256 + ((lc ^ (ln & 7)) << 4);
    const size_t gA = (size_t)ln * Dn + bi * 128 + lc * 8;
    const size_t gB = (size_t)ln * Dn + bj * 128 + lc * 8;

    const int q = lane >> 3, r8 = lane & 7;
    u32 aoff[4], boff[2];
    #pragma unroll
    for (int i = 0; i < 4; ++i) {
        int colh = wm * 64 + (i << 4) + ((q & 1) << 3);
        int row  = ((q >> 1) << 3) + r8;
        aoff[i] = row * 256 + ((((u32)colh >> 3) ^ (row & 7)) << 4);
    }
    #pragma unroll
    for (int p = 0; p < 2; ++p) {
        int colh = wn * 32 + (p << 4) + ((q >> 1) << 3);
        int row  = ((q & 1) << 3) + r8;
        boff[p] = row * 256 + ((((u32)colh >> 3) ^ (row & 7)) << 4);
    }

    const u32 smem_base = (u32)__cvta_generic_to_shared(&smt[0][0][0]);

    auto issue = [&](int stage, int n0) {
        size_t adv = (size_t)n0 * Dn;
        u32 d = smem_base + stage * 16384 + sw_off;
        cpasync16(d + 0 * 4096, g_xh + gA + adv);
        cpasync16(d + 1 * 4096, g_xl + gA + adv);
        cpasync16(d + 2 * 4096, g_xh + gB + adv);
        cpasync16(d + 3 * 4096, g_xl + gB + adv);
        asm volatile("cp.async.commit_group;" ::: "memory");
    };

    issue(0, 0);
    issue(1, 16);

    const int NCHUNK = Nn / 16;   // 512
    for (int ci = 0; ci < NCHUNK; ++ci) {
        asm volatile("cp.async.wait_group 1;" ::: "memory");
        __syncthreads();
        const u32 tb = smem_base + (ci % 3) * 16384;
        u32 Ah[4][4], Al[4][4], Bh[4][2], Bl[4][2];
        #pragma unroll
        for (int i = 0; i < 4; ++i) {
            ldsm4t(Ah[i][0], Ah[i][1], Ah[i][2], Ah[i][3], tb + 0 * 4096 + aoff[i]);
            ldsm4t(Al[i][0], Al[i][1], Al[i][2], Al[i][3], tb + 1 * 4096 + aoff[i]);
        }
        #pragma unroll
        for (int p = 0; p < 2; ++p) {
            ldsm4t(Bh[2 * p][0], Bh[2 * p][1], Bh[2 * p + 1][0], Bh[2 * p + 1][1],
                   tb + 2 * 4096 + boff[p]);
            ldsm4t(Bl[2 * p][0], Bl[2 * p][1], Bl[2 * p + 1][0], Bl[2 * p + 1][1],
                   tb + 3 * 4096 + boff[p]);
        }
        #pragma unroll
        for (int i = 0; i < 4; ++i)
            #pragma unroll
            for (int j = 0; j < 4; ++j) {
                mma16816(acc[i][j], Ah[i], Bh[j]);
                mma16816(acc[i][j], Ah[i], Bl[j]);
                mma16816(acc[i][j], Al[i], Bh[j]);
            }
        if (ci + 2 < NCHUNK) issue((ci + 2) % 3, (ci + 2) * 16);
    }

    const int row0 = lane >> 2, col0 = (lane & 3) * 2;
    #pragma unroll
    for (int i = 0; i < 4; ++i) {
        #pragma unroll
        for (int j = 0; j < 4; ++j) {
            int gi = bi * 128 + wm * 64 + i * 16 + row0;
            int gj = bj * 128 + wn * 32 + j * 8 + col0;
            *(float2*)(g_C + (size_t)gi * Dn + gj) =
                make_float2(acc[i][j][0], acc[i][j][1]);
            *(float2*)(g_C + (size_t)(gi + 8) * Dn + gj) =
                make_float2(acc[i][j][2], acc[i][j][3]);
            if (bi != bj) {
                g_C[(size_t)gj * Dn + gi]           = acc[i][j][0];
                g_C[(size_t)(gj + 1) * Dn + gi]     = acc[i][j][1];
                g_C[(size_t)gj * Dn + gi + 8]       = acc[i][j][2];
                g_C[(size_t)(gj + 1) * Dn + gi + 8] = acc[i][j][3];
            }
        }
    }
}

// ---------------- persistent sequential CCIPCA solve (R13 form) ---------------
__global__ void __launch_bounds__(256) solve_kernel() {
    extern __shared__ __align__(16) float s_dyn[];
    float* s_C   = s_dyn;
    float* s_WT  = s_dyn + ROWS_PB * Dn;
    float* s_VnT = s_dyn + ROWS_PB * Dn + ROWS_PB * Kn;
    __shared__ __align__(16) float s_a[Dn];
    __shared__ float sc3s[Kn], sc1[Kn], s_g[Kn];
    __shared__ float s_b[16], s_u[16], s_vk1[16];

    const int tid = threadIdx.x;
    const int bid = blockIdx.x;
    const int wid = tid >> 5, lane = tid & 31;
    int d_lo = bid * ROWS_PB; if (d_lo > Dn) d_lo = Dn;
    int d_hi = d_lo + ROWS_PB; if (d_hi > Dn) d_hi = Dn;
    const int nrows = d_hi - d_lo;
    unsigned gen = 0;

    {
        const float4* src = (const float4*)&g_C[(size_t)d_lo * Dn];
        float4* dst = (float4*)s_C;
        for (int i = tid; i < nrows * (Dn / 4); i += 256) dst[i] = src[i];
    }
    __syncthreads();

    for (int k = 0; k < Kn; ++k) {
        const int pin = k & 1, pout = pin ^ 1;

        // ---------------- P1 ----------------
        float s = 0.f, c1k1 = 0.f;
        if (k > 0) {
            s = rsqrtf(g_dn2[pin]);
            c1k1 = s * g_uv[pin];
            for (int j = tid; j < k - 1; j += 256) {
                sc3s[j] = g_c3[pin][j] * s;
                sc1[j]  = g_c1[pin][j];
            }
        }
        if (bid == NBLK - 1) {   // block 147 owns 0 rows: zeroing duty
            for (int j = tid; j < Kn; j += 256) {
                g_c3[pout][j] = 0.f;
                g_c1[pout][j] = 0.f;
                g_g[j] = 0.f;
            }
            if (tid == 0) { g_dn2[pout] = 0.f; g_uv[pout] = 0.f; }
        }
        __syncthreads();

        if (k == 0) {
            for (int d = d_lo + tid; d < d_hi; d += 256)
                g_a[d] = g_Vt[d];
        } else {
            for (int dd = wid; dd < nrows; dd += 8) {
                int d = d_lo + dd;
                float u_d = s_u[dd];
                const float* wrow = &s_WT[dd * Kn];
                float sum1 = 0.f, sum2 = 0.f;
                #pragma unroll 4
                for (int j = lane; j < k - 1; j += 32) {
                    float wj = wrow[j];
                    sum1 += sc3s[j] * wj;
                    sum2 += sc1[j] * wj;
                }
                #pragma unroll
                for (int o = 16; o; o >>= 1) {
                    sum1 += __shfl_down_sync(~0u, sum1, o);
                    sum2 += __shfl_down_sync(~0u, sum2, o);
                }
                if (lane == 0) {
                    float vn_d = s * u_d;
                    float w_d = vn_d - sum1;
                    s_VnT[dd * Kn + (k - 1)] = vn_d;
                    s_WT[dd * Kn + (k - 1)] = w_d;
                    __nv_bfloat16 vh = __float2bfloat16(vn_d);
                    g_Vh[(size_t)d * Kn + (k - 1)] = vh;
                    g_Vl[(size_t)d * Kn + (k - 1)] =
                        __float2bfloat16(vn_d - __bfloat162float(vh));
                    g_a[d] = g_Vt[(size_t)k * Dn + d] - sum2 - c1k1 * w_d;
                }
            }
        }
        gbar(gen);

        // ---------------- P2: b = C a (SMEM rows), g_j partials ----------------
        for (int i = tid; i < Dn / 4; i += 256)
            ((float4*)s_a)[i] = ((const float4*)g_a)[i];
        __syncthreads();
        for (int dd = wid; dd < nrows; dd += 8) {
            const float4* crow = (const float4*)&s_C[dd * Dn];
            float sum = 0.f;
            #pragma unroll 4
            for (int t = lane; t < Dn / 4; t += 32) {
                float4 c4 = crow[t];
                float4 a4 = ((const float4*)s_a)[t];
                sum += c4.x * a4.x + c4.y * a4.y + c4.z * a4.z + c4.w * a4.w;
            }
            #pragma unroll
            for (int o = 16; o; o >>= 1) sum += __shfl_down_sync(~0u, sum, o);
            if (lane == 0) s_b[dd] = sum;
        }
        __syncthreads();
        if (tid < k && nrows > 0) {
            float accg = 0.f;
            #pragma unroll 7
            for (int dd = 0; dd < nrows; ++dd)
                accg += s_WT[dd * Kn + tid] * s_b[dd];
            atomicAdd(&g_g[tid], accg);
        }
        gbar(gen);

        // ---------------- P3: u update + next-step dots ----------------
        const float hh = 0.5f / g_d0[k];
        for (int j = tid; j < k; j += 256) s_g[j] = g_g[j];
        __syncthreads();
        for (int dd = wid; dd < nrows; dd += 8) {
            int d = d_lo + dd;
            const float* vrow = &s_VnT[dd * Kn];
            float sumg = 0.f;
            #pragma unroll 4
            for (int j = lane; j < k; j += 32) sumg += s_g[j] * vrow[j];
            #pragma unroll
            for (int o = 16; o; o >>= 1) sumg += __shfl_down_sync(~0u, sumg, o);
            if (lane == 0) {
                float u_d = 0.5f * g_Vt[(size_t)k * Dn + d] + hh * (s_b[dd] - sumg);
                s_u[dd] = u_d;
                s_vk1[dd] = (k + 1 < Kn) ? g_Vt[(size_t)(k + 1) * Dn + d] : 0.f;
            }
        }
        __syncthreads();
        if (tid < k && nrows > 0) {
            float a3 = 0.f, a1 = 0.f;
            #pragma unroll 7
            for (int dd = 0; dd < nrows; ++dd) {
                float vv = s_VnT[dd * Kn + tid];
                a3 += vv * s_u[dd];
                a1 += vv * s_vk1[dd];
            }
            atomicAdd(&g_c3[pout][tid], a3);
            atomicAdd(&g_c1[pout][tid], a1);
        }
        if (tid == 0 && nrows > 0) {
            float d2 = 0.f, uvv = 0.f;
            #pragma unroll 7
            for (int dd = 0; dd < nrows; ++dd) {
                d2  += s_u[dd] * s_u[dd];
                uvv += s_u[dd] * s_vk1[dd];
            }
            atomicAdd(&g_dn2[pout], d2);
            atomicAdd(&g_uv[pout], uvv);
        }
        gbar(gen);
    }

    // epilogue: write vn_{K-1} (bf16 hi/lo)
    {
        const int plast = ((Kn - 1) & 1) ^ 1;
        float sfin = rsqrtf(g_dn2[plast]);
        for (int dd = tid; dd < nrows; dd += 256) {
            float vn_d = sfin * s_u[dd];
            __nv_bfloat16 vh = __float2bfloat16(vn_d);
            g_Vh[(size_t)(d_lo + dd) * Kn + (Kn - 1)] = vh;
            g_Vl[(size_t)(d_lo + dd) * Kn + (Kn - 1)] =
                __float2bfloat16(vn_d - __bfloat162float(vh));
        }
    }

    __syncthreads();
    if (tid == 0) {
        __threadfence();
        if (atomicAdd(&g_done, 1u) == (unsigned)(gridDim.x - 1)) {
            g_done = 0u;
            g_barcnt = 0u;
            __threadfence();
        }
    }
}

// ---------------- out = x @ Vn (tensor cores, bf16 3-term split) --------------
// R11-verified kernel. A frags: non-trans ldmatrix on natural [m][d] tiles
// (48B padded pitch). B frags: trans ldmatrix on swizzled [d][j] tiles.
__global__ void __launch_bounds__(256, 2) gemmOut_tc_kernel(float* __restrict__ out) {
    __shared__ __align__(16) u16 sa[2][2][128][24];
    __shared__ __align__(16) u16 sb[2][2][16][64];

    const int bm = blockIdx.x >> 2;
    const int bj = blockIdx.x & 3;
    const int tid = threadIdx.x;
    const int warp = tid >> 5, lane = tid & 31;
    const int wm = warp >> 2, wn = warp & 3;
    const int m0 = bm * 128;

    float acc[4][2][4];
    #pragma unroll
    for (int i = 0; i < 4; ++i)
        #pragma unroll
        for (int j = 0; j < 2; ++j)
            #pragma unroll
            for (int r = 0; r < 4; ++r) acc[i][j][r] = 0.f;

    const int am = tid >> 1, ac = tid & 1;
    const size_t gxa = (size_t)(m0 + am) * Dn + ac * 8;
    const int bmat = tid >> 7;
    const int brr = (tid >> 3) & 15;
    const int bcc = tid & 7;
    const int bsw = (bcc ^ (brr & 7)) * 8;
    const size_t gvb = (size_t)brr * Kn + bj * 64 + bcc * 8;
    const __nv_bfloat16* vsrc = bmat ? g_Vl : g_Vh;

    const int q = lane >> 3, r8 = lane & 7;
    u32 aoff[4];
    #pragma unroll
    for (int i = 0; i < 4; ++i) {
        int row = wm * 64 + i * 16 + ((q & 1) << 3) + r8;
        aoff[i] = (u32)row * 48 + ((u32)(q >> 1) << 4);
    }
    u32 boff;
    {
        int bcol = wn * 16 + ((q >> 1) << 3);
        int brow = ((q & 1) << 3) + r8;
        boff = (u32)brow * 128 + ((((u32)bcol >> 3) ^ (brow & 7)) << 4);
    }
    const u32 sa_base = (u32)__cvta_generic_to_shared(&sa[0][0][0][0]);
    const u32 sb_base = (u32)__cvta_generic_to_shared(&sb[0][0][0][0]);
    const u32 SA_MAT = 128 * 48;
    const u32 SB_MAT = 16 * 128;

    uint4 pah, pal, pbv;
    pah = *(const uint4*)(g_xh + gxa);
    pal = *(const uint4*)(g_xl + gxa);
    pbv = *(const uint4*)(vsrc + gvb);
    *(uint4*)&sa[0][0][am][ac * 8] = pah;
    *(uint4*)&sa[0][1][am][ac * 8] = pal;
    *(uint4*)&sb[0][bmat][brr][bsw] = pbv;
    __syncthreads();

    int buf = 0;
    for (int d0 = 0; d0 < Dn; d0 += 16) {
        const bool more = (d0 + 16 < Dn);
        if (more) {
            pah = *(const uint4*)(g_xh + gxa + (d0 + 16));
            pal = *(const uint4*)(g_xl + gxa + (d0 + 16));
            pbv = *(const uint4*)(vsrc + gvb + (size_t)(d0 + 16) * Kn);
        }
        const u32 ab = sa_base + buf * (2 * SA_MAT);
        const u32 bb = sb_base + buf * (2 * SB_MAT);
        u32 Ah[4][4], Al[4][4], Bh[2][2], Bl[2][2];
        #pragma unroll
        for (int i = 0; i < 4; ++i) {
            ldsm4(Ah[i][0], Ah[i][1], Ah[i][2], Ah[i][3], ab + aoff[i]);
            ldsm4(Al[i][0], Al[i][1], Al[i][2], Al[i][3], ab + SA_MAT + aoff[i]);
        }
        ldsm4t(Bh[0][0], Bh[0][1], Bh[1][0], Bh[1][1], bb + boff);
        ldsm4t(Bl[0][0], Bl[0][1], Bl[1][0], Bl[1][1], bb + SB_MAT + boff);
        #pragma unroll
        for (int i = 0; i < 4; ++i)
            #pragma unroll
            for (int j = 0; j < 2; ++j) {
                mma16816(acc[i][j], Ah[i], Bh[j]);
                mma16816(acc[i][j], Ah[i], Bl[j]);
                mma16816(acc[i][j], Al[i], Bh[j]);
            }
        if (more) {
            int nb = buf ^ 1;
            *(uint4*)&sa[nb][0][am][ac * 8] = pah;
            *(uint4*)&sa[nb][1][am][ac * 8] = pal;
            *(uint4*)&sb[nb][bmat][brr][bsw] = pbv;
        }
        __syncthreads();
        buf ^= 1;
    }

    const int row0 = lane >> 2, col0 = (lane & 3) * 2;
    #pragma unroll
    for (int i = 0; i < 4; ++i)
        #pragma unroll
        for (int j = 0; j < 2; ++j) {
            int gi = m0 + wm * 64 + i * 16 + row0;
            int gj = bj * 64 + wn * 16 + j * 8 + col0;
            *(float2*)(out + (size_t)gi * Kn + gj) =
                make_float2(acc[i][j][0], acc[i][j][1]);
            *(float2*)(out + (size_t)(gi + 8) * Kn + gj) =
                make_float2(acc[i][j][2], acc[i][j][3]);
        }
}

// ---------------- launch ----------------
extern "C" void kernel_launch(void* const* d_in, const int* in_sizes, int n_in,
                              void* d_out, int out_size) {
    const float* x  = (const float*)d_in[0];
    const float* V0 = (const float*)d_in[1];
    if (n_in >= 2 && in_sizes[0] == Dn * Kn && in_sizes[1] == Nn * Dn) {
        const float* t = x; x = V0; V0 = t;
    }
    float* out = (float*)d_out;

    static int smem_set = 0;
    const int dyn_smem = (ROWS_PB * Dn + 2 * ROWS_PB * Kn) * (int)sizeof(float); // 143360
    if (!smem_set) {
        cudaFuncSetAttribute(solve_kernel,
                             cudaFuncAttributeMaxDynamicSharedMemorySize, dyn_smem);
        smem_set = 1;
    }

    splitx_kernel<<<2048, 256>>>(x);
    prep_kernel<<<Kn, 256>>>(V0);
    gemmC_tc_kernel<<<136, 256>>>();
    solve_kernel<<<NBLK, 256, dyn_smem>>>();
    gemmOut_tc_kernel<<<256, 256>>>(out);
}

// round 16
// speedup vs baseline: 1.6517x; 1.0529x over previous
#include <cuda_runtime.h>
#include <cuda_bf16.h>
#include <math.h>

#define Nn 8192
#define Dn 2048
#define Kn 256
#define NBLK 148
#define ROWS_PB 14            // 148 * 14 = 2072 >= 2048

typedef unsigned long long ull;
typedef unsigned int u32;
typedef unsigned short u16;

// ---------------- device scratch (static: no allocation allowed) ----------------
__device__ float g_C[(size_t)Dn * Dn];          // 16 MB  C = x^T x (L2-resident)
__device__ __nv_bfloat16 g_xh[(size_t)Nn * Dn]; // 32 MB hi split of x
__device__ __nv_bfloat16 g_xl[(size_t)Nn * Dn]; // 32 MB lo split of x
__device__ __nv_bfloat16 g_Vh[(size_t)Dn * Kn]; // 1 MB  hi split of Vn
__device__ __nv_bfloat16 g_Vl[(size_t)Dn * Kn]; // 1 MB  lo split of Vn
__device__ float g_Vt[(size_t)Kn * Dn];
__device__ float g_a[Dn];
__device__ float g_c1[2][Kn];
__device__ float g_c3[2][Kn];
__device__ float g_g[Kn];
__device__ float g_d0[Kn];
__device__ float g_dn2[2];
__device__ float g_uv[2];
__device__ __align__(128) unsigned g_barcnt;   // single counter (measured best)
__device__ __align__(128) unsigned g_done;

// ---------------- grid barrier: R3 single counter + polite poll (best) --------
__device__ __forceinline__ void gbar(unsigned& gen) {
    gen += gridDim.x;
    __syncthreads();
    if (threadIdx.x == 0) {
        asm volatile("red.release.gpu.global.add.u32 [%0], 1;"
                     :: "l"(&g_barcnt) : "memory");
        unsigned v;
        asm volatile("ld.relaxed.gpu.global.u32 %0, [%1];"
                     : "=r"(v) : "l"(&g_barcnt) : "memory");
        while ((int)(v - gen) < 0) {
            __nanosleep(64);
            asm volatile("ld.relaxed.gpu.global.u32 %0, [%1];"
                         : "=r"(v) : "l"(&g_barcnt) : "memory");
        }
        asm volatile("ld.acquire.gpu.global.u32 %0, [%1];"
                     : "=r"(v) : "l"(&g_barcnt) : "memory");
    }
    __syncthreads();
}

// ---------------- cp.async helper ----------------
__device__ __forceinline__ void cpasync16(u32 saddr, const void* gaddr) {
    asm volatile("cp.async.cg.shared.global [%0], [%1], 16;"
                 :: "r"(saddr), "l"(gaddr) : "memory");
}

// ---------------- split x into bf16 hi + lo ----------------
__global__ void __launch_bounds__(256) splitx_kernel(const float* __restrict__ x) {
    const int stride = gridDim.x * 256;
    for (int i = blockIdx.x * 256 + threadIdx.x; i < Nn * Dn / 4; i += stride) {
        float4 v = ((const float4*)x)[i];
        __nv_bfloat16 h0 = __float2bfloat16(v.x);
        __nv_bfloat16 h1 = __float2bfloat16(v.y);
        __nv_bfloat16 h2 = __float2bfloat16(v.z);
        __nv_bfloat16 h3 = __float2bfloat16(v.w);
        __nv_bfloat16 l0 = __float2bfloat16(v.x - __bfloat162float(h0));
        __nv_bfloat16 l1 = __float2bfloat16(v.y - __bfloat162float(h1));
        __nv_bfloat16 l2 = __float2bfloat16(v.z - __bfloat162float(h2));
        __nv_bfloat16 l3 = __float2bfloat16(v.w - __bfloat162float(h3));
        ushort4 hh, ll;
        hh.x = *(u16*)&h0; hh.y = *(u16*)&h1; hh.z = *(u16*)&h2; hh.w = *(u16*)&h3;
        ll.x = *(u16*)&l0; ll.y = *(u16*)&l1; ll.z = *(u16*)&l2; ll.w = *(u16*)&l3;
        ((ushort4*)g_xh)[i] = hh;
        ((ushort4*)g_xl)[i] = ll;
    }
}

// ---------------- prep: transpose V0 -> Vt, per-column norms d0 ----------------
__global__ void __launch_bounds__(256) prep_kernel(const float* __restrict__ V0) {
    __shared__ float sb[8];
    int k = blockIdx.x;
    float s = 0.f;
    for (int d = threadIdx.x; d < Dn; d += 256) {
        float v = V0[(size_t)d * Kn + k];
        g_Vt[(size_t)k * Dn + d] = v;
        s += v * v;
    }
    #pragma unroll
    for (int o = 16; o; o >>= 1) s += __shfl_down_sync(~0u, s, o);
    if ((threadIdx.x & 31) == 0) sb[threadIdx.x >> 5] = s;
    __syncthreads();
    if (threadIdx.x == 0) {
        float t = 0.f;
        #pragma unroll
        for (int w = 0; w < 8; ++w) t += sb[w];
        g_d0[k] = sqrtf(t);
    }
}

// ---------------- tensor-core helpers ----------------
__device__ __forceinline__ void ldsm4t(u32& r0, u32& r1, u32& r2, u32& r3, u32 addr) {
    asm volatile("ldmatrix.sync.aligned.m8n8.x4.trans.shared.b16 {%0,%1,%2,%3}, [%4];"
                 : "=r"(r0), "=r"(r1), "=r"(r2), "=r"(r3) : "r"(addr));
}
__device__ __forceinline__ void ldsm4(u32& r0, u32& r1, u32& r2, u32& r3, u32 addr) {
    asm volatile("ldmatrix.sync.aligned.m8n8.x4.shared.b16 {%0,%1,%2,%3}, [%4];"
                 : "=r"(r0), "=r"(r1), "=r"(r2), "=r"(r3) : "r"(addr));
}
__device__ __forceinline__ void mma16816(float* c, const u32* a, const u32* b) {
    asm volatile(
        "mma.sync.aligned.m16n8k16.row.col.f32.bf16.bf16.f32 "
        "{%0,%1,%2,%3}, {%4,%5,%6,%7}, {%8,%9}, {%0,%1,%2,%3};"
        : "+f"(c[0]), "+f"(c[1]), "+f"(c[2]), "+f"(c[3])
        : "r"(a[0]), "r"(a[1]), "r"(a[2]), "r"(a[3]), "r"(b[0]), "r"(b[1]));
}

// ---------------- C = xh^T xh + xh^T xl + xl^T xh (TC, 3-stage cp.async) ------
__global__ void __launch_bounds__(256) gemmC_tc_kernel() {
    __shared__ __align__(16) char smt[3][4][16 * 256];   // 48 KB

    int rem = blockIdx.x, bi = 0, width = 16;
    while (rem >= width) { rem -= width; ++bi; --width; }
    int bj = bi + rem;

    const int tid = threadIdx.x;
    const int warp = tid >> 5, lane = tid & 31;
    const int wm = warp >> 2, wn = warp & 3;

    float acc[4][4][4];
    #pragma unroll
    for (int i = 0; i < 4; ++i)
        #pragma unroll
        for (int j = 0; j < 4; ++j)
            #pragma unroll
            for (int r = 0; r < 4; ++r) acc[i][j][r] = 0.f;

    const int ln = tid >> 4;
    const int lc = tid & 15;
    const u32 sw_off = ln * 256 + ((lc ^ (ln & 7)) << 4);
    const size_t gA = (size_t)ln * Dn + bi * 128 + lc * 8;
    const size_t gB = (size_t)ln * Dn + bj * 128 + lc * 8;

    const int q = lane >> 3, r8 = lane & 7;
    u32 aoff[4], boff[2];
    #pragma unroll
    for (int i = 0; i < 4; ++i) {
        int colh = wm * 64 + (i << 4) + ((q & 1) << 3);
        int row  = ((q >> 1) << 3) + r8;
        aoff[i] = row * 256 + ((((u32)colh >> 3) ^ (row & 7)) << 4);
    }
    #pragma unroll
    for (int p = 0; p < 2; ++p) {
        int colh = wn * 32 + (p << 4) + ((q >> 1) << 3);
        int row  = ((q & 1) << 3) + r8;
        boff[p] = row * 256 + ((((u32)colh >> 3) ^ (row & 7)) << 4);
    }

    const u32 smem_base = (u32)__cvta_generic_to_shared(&smt[0][0][0]);

    auto issue = [&](int stage, int n0) {
        size_t adv = (size_t)n0 * Dn;
        u32 d = smem_base + stage * 16384 + sw_off;
        cpasync16(d + 0 * 4096, g_xh + gA + adv);
        cpasync16(d + 1 * 4096, g_xl + gA + adv);
        cpasync16(d + 2 * 4096, g_xh + gB + adv);
        cpasync16(d + 3 * 4096, g_xl + gB + adv);
        asm volatile("cp.async.commit_group;" ::: "memory");
    };

    issue(0, 0);
    issue(1, 16);

    const int NCHUNK = Nn / 16;   // 512
    for (int ci = 0; ci < NCHUNK; ++ci) {
        asm volatile("cp.async.wait_group 1;" ::: "memory");
        __syncthreads();
        const u32 tb = smem_base + (ci % 3) * 16384;
        u32 Ah[4][4], Al[4][4], Bh[4][2], Bl[4][2];
        #pragma unroll
        for (int i = 0; i < 4; ++i) {
            ldsm4t(Ah[i][0], Ah[i][1], Ah[i][2], Ah[i][3], tb + 0 * 4096 + aoff[i]);
            ldsm4t(Al[i][0], Al[i][1], Al[i][2], Al[i][3], tb + 1 * 4096 + aoff[i]);
        }
        #pragma unroll
        for (int p = 0; p < 2; ++p) {
            ldsm4t(Bh[2 * p][0], Bh[2 * p][1], Bh[2 * p + 1][0], Bh[2 * p + 1][1],
                   tb + 2 * 4096 + boff[p]);
            ldsm4t(Bl[2 * p][0], Bl[2 * p][1], Bl[2 * p + 1][0], Bl[2 * p + 1][1],
                   tb + 3 * 4096 + boff[p]);
        }
        #pragma unroll
        for (int i = 0; i < 4; ++i)
            #pragma unroll
            for (int j = 0; j < 4; ++j) {
                mma16816(acc[i][j], Ah[i], Bh[j]);
                mma16816(acc[i][j], Ah[i], Bl[j]);
                mma16816(acc[i][j], Al[i], Bh[j]);
            }
        if (ci + 2 < NCHUNK) issue((ci + 2) % 3, (ci + 2) * 16);
    }

    const int row0 = lane >> 2, col0 = (lane & 3) * 2;
    #pragma unroll
    for (int i = 0; i < 4; ++i) {
        #pragma unroll
        for (int j = 0; j < 4; ++j) {
            int gi = bi * 128 + wm * 64 + i * 16 + row0;
            int gj = bj * 128 + wn * 32 + j * 8 + col0;
            *(float2*)(g_C + (size_t)gi * Dn + gj) =
                make_float2(acc[i][j][0], acc[i][j][1]);
            *(float2*)(g_C + (size_t)(gi + 8) * Dn + gj) =
                make_float2(acc[i][j][2], acc[i][j][3]);
            if (bi != bj) {
                g_C[(size_t)gj * Dn + gi]           = acc[i][j][0];
                g_C[(size_t)(gj + 1) * Dn + gi]     = acc[i][j][1];
                g_C[(size_t)gj * Dn + gi + 8]       = acc[i][j][2];
                g_C[(size_t)(gj + 1) * Dn + gi + 8] = acc[i][j][3];
            }
        }
    }
}

// ---------------- persistent sequential CCIPCA solve (512 thr, 1 row/warp) ----
__global__ void __launch_bounds__(512) solve_kernel() {
    extern __shared__ __align__(16) float s_dyn[];
    float* s_C   = s_dyn;
    float* s_WT  = s_dyn + ROWS_PB * Dn;
    float* s_VnT = s_dyn + ROWS_PB * Dn + ROWS_PB * Kn;
    __shared__ __align__(16) float s_a[Dn];
    __shared__ float sc3s[Kn], sc1[Kn], s_g[Kn];
    __shared__ float s_b[16], s_u[16], s_vk1[16];

    const int tid = threadIdx.x;
    const int bid = blockIdx.x;
    const int wid = tid >> 5, lane = tid & 31;
    int d_lo = bid * ROWS_PB; if (d_lo > Dn) d_lo = Dn;
    int d_hi = d_lo + ROWS_PB; if (d_hi > Dn) d_hi = Dn;
    const int nrows = d_hi - d_lo;
    unsigned gen = 0;

    {
        const float4* src = (const float4*)&g_C[(size_t)d_lo * Dn];
        float4* dst = (float4*)s_C;
        for (int i = tid; i < nrows * (Dn / 4); i += 512) dst[i] = src[i];
    }
    __syncthreads();

    for (int k = 0; k < Kn; ++k) {
        const int pin = k & 1, pout = pin ^ 1;

        // ---------------- P1 ----------------
        float s = 0.f, c1k1 = 0.f;
        if (k > 0) {
            s = rsqrtf(g_dn2[pin]);
            c1k1 = s * g_uv[pin];
            for (int j = tid; j < k - 1; j += 512) {
                sc3s[j] = g_c3[pin][j] * s;
                sc1[j]  = g_c1[pin][j];
            }
        }
        if (bid == NBLK - 1) {   // block 147 owns 0 rows: zeroing duty
            for (int j = tid; j < Kn; j += 512) {
                g_c3[pout][j] = 0.f;
                g_c1[pout][j] = 0.f;
                g_g[j] = 0.f;
            }
            if (tid == 0) { g_dn2[pout] = 0.f; g_uv[pout] = 0.f; }
        }
        __syncthreads();

        if (k == 0) {
            for (int dd = tid; dd < nrows; dd += 512)
                g_a[d_lo + dd] = g_Vt[d_lo + dd];
        } else if (wid < nrows) {
            const int dd = wid;
            const int d = d_lo + dd;
            float u_d = s_u[dd];
            const float* wrow = &s_WT[dd * Kn];
            float sum1 = 0.f, sum2 = 0.f;
            #pragma unroll 4
            for (int j = lane; j < k - 1; j += 32) {
                float wj = wrow[j];
                sum1 += sc3s[j] * wj;
                sum2 += sc1[j] * wj;
            }
            #pragma unroll
            for (int o = 16; o; o >>= 1) {
                sum1 += __shfl_down_sync(~0u, sum1, o);
                sum2 += __shfl_down_sync(~0u, sum2, o);
            }
            if (lane == 0) {
                float vn_d = s * u_d;
                float w_d = vn_d - sum1;
                s_VnT[dd * Kn + (k - 1)] = vn_d;
                s_WT[dd * Kn + (k - 1)] = w_d;
                __nv_bfloat16 vh = __float2bfloat16(vn_d);
                g_Vh[(size_t)d * Kn + (k - 1)] = vh;
                g_Vl[(size_t)d * Kn + (k - 1)] =
                    __float2bfloat16(vn_d - __bfloat162float(vh));
                g_a[d] = g_Vt[(size_t)k * Dn + d] - sum2 - c1k1 * w_d;
            }
        }
        gbar(gen);

        // ---------------- P2: b = C a (SMEM rows), g_j partials ----------------
        if (tid < Dn / 4)
            ((float4*)s_a)[tid] = ((const float4*)g_a)[tid];
        __syncthreads();
        if (wid < nrows) {
            const int dd = wid;
            const float4* crow = (const float4*)&s_C[dd * Dn];
            float s0 = 0.f, s1 = 0.f, s2 = 0.f, s3 = 0.f;
            #pragma unroll 4
            for (int t = lane; t < Dn / 4; t += 32) {
                float4 c4 = crow[t];
                float4 a4 = ((const float4*)s_a)[t];
                s0 = fmaf(c4.x, a4.x, s0);
                s1 = fmaf(c4.y, a4.y, s1);
                s2 = fmaf(c4.z, a4.z, s2);
                s3 = fmaf(c4.w, a4.w, s3);
            }
            float sum = (s0 + s1) + (s2 + s3);
            #pragma unroll
            for (int o = 16; o; o >>= 1) sum += __shfl_down_sync(~0u, sum, o);
            if (lane == 0) s_b[dd] = sum;
        }
        __syncthreads();
        if (tid < k && nrows > 0) {
            float accg = 0.f;
            #pragma unroll 7
            for (int dd = 0; dd < nrows; ++dd)
                accg += s_WT[dd * Kn + tid] * s_b[dd];
            atomicAdd(&g_g[tid], accg);
        }
        gbar(gen);

        // ---------------- P3: u update + next-step dots ----------------
        const float hh = 0.5f / g_d0[k];
        for (int j = tid; j < k; j += 512) s_g[j] = g_g[j];
        __syncthreads();
        if (wid < nrows) {
            const int dd = wid;
            const int d = d_lo + dd;
            const float* vrow = &s_VnT[dd * Kn];
            float sumg = 0.f;
            #pragma unroll 4
            for (int j = lane; j < k; j += 32) sumg += s_g[j] * vrow[j];
            #pragma unroll
            for (int o = 16; o; o >>= 1) sumg += __shfl_down_sync(~0u, sumg, o);
            if (lane == 0) {
                float u_d = 0.5f * g_Vt[(size_t)k * Dn + d] + hh * (s_b[dd] - sumg);
                s_u[dd] = u_d;
                s_vk1[dd] = (k + 1 < Kn) ? g_Vt[(size_t)(k + 1) * Dn + d] : 0.f;
            }
        }
        __syncthreads();
        if (tid < k && nrows > 0) {
            float a3 = 0.f, a1 = 0.f;
            #pragma unroll 7
            for (int dd = 0; dd < nrows; ++dd) {
                float vv = s_VnT[dd * Kn + tid];
                a3 += vv * s_u[dd];
                a1 += vv * s_vk1[dd];
            }
            atomicAdd(&g_c3[pout][tid], a3);
            atomicAdd(&g_c1[pout][tid], a1);
        }
        if (tid == 0 && nrows > 0) {
            float d2 = 0.f, uvv = 0.f;
            #pragma unroll 7
            for (int dd = 0; dd < nrows; ++dd) {
                d2  += s_u[dd] * s_u[dd];
                uvv += s_u[dd] * s_vk1[dd];
            }
            atomicAdd(&g_dn2[pout], d2);
            atomicAdd(&g_uv[pout], uvv);
        }
        gbar(gen);
    }

    // epilogue: write vn_{K-1} (bf16 hi/lo)
    {
        const int plast = ((Kn - 1) & 1) ^ 1;
        float sfin = rsqrtf(g_dn2[plast]);
        for (int dd = tid; dd < nrows; dd += 512) {
            float vn_d = sfin * s_u[dd];
            __nv_bfloat16 vh = __float2bfloat16(vn_d);
            g_Vh[(size_t)(d_lo + dd) * Kn + (Kn - 1)] = vh;
            g_Vl[(size_t)(d_lo + dd) * Kn + (Kn - 1)] =
                __float2bfloat16(vn_d - __bfloat162float(vh));
        }
    }

    __syncthreads();
    if (tid == 0) {
        __threadfence();
        if (atomicAdd(&g_done, 1u) == (unsigned)(gridDim.x - 1)) {
            g_done = 0u;
            g_barcnt = 0u;
            __threadfence();
        }
    }
}

// ---------------- out = x @ Vn (tensor cores, bf16 3-term split) --------------
__global__ void __launch_bounds__(256, 2) gemmOut_tc_kernel(float* __restrict__ out) {
    __shared__ __align__(16) u16 sa[2][2][128][24];
    __shared__ __align__(16) u16 sb[2][2][16][64];

    const int bm = blockIdx.x >> 2;
    const int bj = blockIdx.x & 3;
    const int tid = threadIdx.x;
    const int warp = tid >> 5, lane = tid & 31;
    const int wm = warp >> 2, wn = warp & 3;
    const int m0 = bm * 128;

    float acc[4][2][4];
    #pragma unroll
    for (int i = 0; i < 4; ++i)
        #pragma unroll
        for (int j = 0; j < 2; ++j)
            #pragma unroll
            for (int r = 0; r < 4; ++r) acc[i][j][r] = 0.f;

    const int am = tid >> 1, ac = tid & 1;
    const size_t gxa = (size_t)(m0 + am) * Dn + ac * 8;
    const int bmat = tid >> 7;
    const int brr = (tid >> 3) & 15;
    const int bcc = tid & 7;
    const int bsw = (bcc ^ (brr & 7)) * 8;
    const size_t gvb = (size_t)brr * Kn + bj * 64 + bcc * 8;
    const __nv_bfloat16* vsrc = bmat ? g_Vl : g_Vh;

    const int q = lane >> 3, r8 = lane & 7;
    u32 aoff[4];
    #pragma unroll
    for (int i = 0; i < 4; ++i) {
        int row = wm * 64 + i * 16 + ((q & 1) << 3) + r8;
        aoff[i] = (u32)row * 48 + ((u32)(q >> 1) << 4);
    }
    u32 boff;
    {
        int bcol = wn * 16 + ((q >> 1) << 3);
        int brow = ((q & 1) << 3) + r8;
        boff = (u32)brow * 128 + ((((u32)bcol >> 3) ^ (brow & 7)) << 4);
    }
    const u32 sa_base = (u32)__cvta_generic_to_shared(&sa[0][0][0][0]);
    const u32 sb_base = (u32)__cvta_generic_to_shared(&sb[0][0][0][0]);
    const u32 SA_MAT = 128 * 48;
    const u32 SB_MAT = 16 * 128;

    uint4 pah, pal, pbv;
    pah = *(const uint4*)(g_xh + gxa);
    pal = *(const uint4*)(g_xl + gxa);
    pbv = *(const uint4*)(vsrc + gvb);
    *(uint4*)&sa[0][0][am][ac * 8] = pah;
    *(uint4*)&sa[0][1][am][ac * 8] = pal;
    *(uint4*)&sb[0][bmat][brr][bsw] = pbv;
    __syncthreads();

    int buf = 0;
    for (int d0 = 0; d0 < Dn; d0 += 16) {
        const bool more = (d0 + 16 < Dn);
        if (more) {
            pah = *(const uint4*)(g_xh + gxa + (d0 + 16));
            pal = *(const uint4*)(g_xl + gxa + (d0 + 16));
            pbv = *(const uint4*)(vsrc + gvb + (size_t)(d0 + 16) * Kn);
        }
        const u32 ab = sa_base + buf * (2 * SA_MAT);
        const u32 bb = sb_base + buf * (2 * SB_MAT);
        u32 Ah[4][4], Al[4][4], Bh[2][2], Bl[2][2];
        #pragma unroll
        for (int i = 0; i < 4; ++i) {
            ldsm4(Ah[i][0], Ah[i][1], Ah[i][2], Ah[i][3], ab + aoff[i]);
            ldsm4(Al[i][0], Al[i][1], Al[i][2], Al[i][3], ab + SA_MAT + aoff[i]);
        }
        ldsm4t(Bh[0][0], Bh[0][1], Bh[1][0], Bh[1][1], bb + boff);
        ldsm4t(Bl[0][0], Bl[0][1], Bl[1][0], Bl[1][1], bb + SB_MAT + boff);
        #pragma unroll
        for (int i = 0; i < 4; ++i)
            #pragma unroll
            for (int j = 0; j < 2; ++j) {
                mma16816(acc[i][j], Ah[i], Bh[j]);
                mma16816(acc[i][j], Ah[i], Bl[j]);
                mma16816(acc[i][j], Al[i], Bh[j]);
            }
        if (more) {
            int nb = buf ^ 1;
            *(uint4*)&sa[nb][0][am][ac * 8] = pah;
            *(uint4*)&sa[nb][1][am][ac * 8] = pal;
            *(uint4*)&sb[nb][bmat][brr][bsw] = pbv;
        }
        __syncthreads();
        buf ^= 1;
    }

    const int row0 = lane >> 2, col0 = (lane & 3) * 2;
    #pragma unroll
    for (int i = 0; i < 4; ++i)
        #pragma unroll
        for (int j = 0; j < 2; ++j) {
            int gi = m0 + wm * 64 + i * 16 + row0;
            int gj = bj * 64 + wn * 16 + j * 8 + col0;
            *(float2*)(out + (size_t)gi * Kn + gj) =
                make_float2(acc[i][j][0], acc[i][j][1]);
            *(float2*)(out + (size_t)(gi + 8) * Kn + gj) =
                make_float2(acc[i][j][2], acc[i][j][3]);
        }
}

// ---------------- launch ----------------
extern "C" void kernel_launch(void* const* d_in, const int* in_sizes, int n_in,
                              void* d_out, int out_size) {
    const float* x  = (const float*)d_in[0];
    const float* V0 = (const float*)d_in[1];
    if (n_in >= 2 && in_sizes[0] == Dn * Kn && in_sizes[1] == Nn * Dn) {
        const float* t = x; x = V0; V0 = t;
    }
    float* out = (float*)d_out;

    static int smem_set = 0;
    const int dyn_smem = (ROWS_PB * Dn + 2 * ROWS_PB * Kn) * (int)sizeof(float); // 143360
    if (!smem_set) {
        cudaFuncSetAttribute(solve_kernel,
                             cudaFuncAttributeMaxDynamicSharedMemorySize, dyn_smem);
        smem_set = 1;
    }

    splitx_kernel<<<2048, 256>>>(x);
    prep_kernel<<<Kn, 256>>>(V0);
    gemmC_tc_kernel<<<136, 256>>>();
    solve_kernel<<<NBLK, 512, dyn_smem>>>();
    gemmOut_tc_kernel<<<256, 256>>>(out);
}

// round 17
// speedup vs baseline: 1.6939x; 1.0255x over previous
#include <cuda_runtime.h>
#include <cuda_bf16.h>
#include <math.h>

#define Nn 8192
#define Dn 2048
#define Kn 256
#define NBLK 148
#define ROWS_PB 14            // 148 * 14 = 2072 >= 2048

typedef unsigned long long ull;
typedef unsigned int u32;
typedef unsigned short u16;

// ---------------- device scratch (static: no allocation allowed) ----------------
__device__ float g_C[(size_t)Dn * Dn];          // 16 MB  C = x^T x (L2-resident)
__device__ __nv_bfloat16 g_xh[(size_t)Nn * Dn]; // 32 MB hi split of x
__device__ __nv_bfloat16 g_xl[(size_t)Nn * Dn]; // 32 MB lo split of x
__device__ __nv_bfloat16 g_Vh[(size_t)Dn * Kn]; // 1 MB  hi split of Vn
__device__ __nv_bfloat16 g_Vl[(size_t)Dn * Kn]; // 1 MB  lo split of Vn
__device__ float g_Vt[(size_t)Kn * Dn];
__device__ float g_a[Dn];
__device__ float g_c1[2][Kn];
__device__ float g_c3[2][Kn];
__device__ float g_g[Kn];
__device__ float g_d0[Kn];
__device__ float g_dn2[2];
__device__ float g_uv[2];
__device__ __align__(128) unsigned g_barcnt;   // single counter (measured best)
__device__ __align__(128) unsigned g_done;

// ---------------- grid barrier: R3 single counter + polite poll (best) --------
__device__ __forceinline__ void gbar(unsigned& gen) {
    gen += gridDim.x;
    __syncthreads();
    if (threadIdx.x == 0) {
        asm volatile("red.release.gpu.global.add.u32 [%0], 1;"
                     :: "l"(&g_barcnt) : "memory");
        unsigned v;
        asm volatile("ld.relaxed.gpu.global.u32 %0, [%1];"
                     : "=r"(v) : "l"(&g_barcnt) : "memory");
        while ((int)(v - gen) < 0) {
            __nanosleep(64);
            asm volatile("ld.relaxed.gpu.global.u32 %0, [%1];"
                         : "=r"(v) : "l"(&g_barcnt) : "memory");
        }
        asm volatile("ld.acquire.gpu.global.u32 %0, [%1];"
                     : "=r"(v) : "l"(&g_barcnt) : "memory");
    }
    __syncthreads();
}

// ---------------- cp.async helper ----------------
__device__ __forceinline__ void cpasync16(u32 saddr, const void* gaddr) {
    asm volatile("cp.async.cg.shared.global [%0], [%1], 16;"
                 :: "r"(saddr), "l"(gaddr) : "memory");
}

// ---------------- split x into bf16 hi + lo ----------------
__global__ void __launch_bounds__(256) splitx_kernel(const float* __restrict__ x) {
    const int stride = gridDim.x * 256;
    for (int i = blockIdx.x * 256 + threadIdx.x; i < Nn * Dn / 4; i += stride) {
        float4 v = ((const float4*)x)[i];
        __nv_bfloat16 h0 = __float2bfloat16(v.x);
        __nv_bfloat16 h1 = __float2bfloat16(v.y);
        __nv_bfloat16 h2 = __float2bfloat16(v.z);
        __nv_bfloat16 h3 = __float2bfloat16(v.w);
        __nv_bfloat16 l0 = __float2bfloat16(v.x - __bfloat162float(h0));
        __nv_bfloat16 l1 = __float2bfloat16(v.y - __bfloat162float(h1));
        __nv_bfloat16 l2 = __float2bfloat16(v.z - __bfloat162float(h2));
        __nv_bfloat16 l3 = __float2bfloat16(v.w - __bfloat162float(h3));
        ushort4 hh, ll;
        hh.x = *(u16*)&h0; hh.y = *(u16*)&h1; hh.z = *(u16*)&h2; hh.w = *(u16*)&h3;
        ll.x = *(u16*)&l0; ll.y = *(u16*)&l1; ll.z = *(u16*)&l2; ll.w = *(u16*)&l3;
        ((ushort4*)g_xh)[i] = hh;
        ((ushort4*)g_xl)[i] = ll;
    }
}

// ---------------- prep: transpose V0 -> Vt, per-column norms d0 ----------------
__global__ void __launch_bounds__(256) prep_kernel(const float* __restrict__ V0) {
    __shared__ float sb[8];
    int k = blockIdx.x;
    float s = 0.f;
    for (int d = threadIdx.x; d < Dn; d += 256) {
        float v = V0[(size_t)d * Kn + k];
        g_Vt[(size_t)k * Dn + d] = v;
        s += v * v;
    }
    #pragma unroll
    for (int o = 16; o; o >>= 1) s += __shfl_down_sync(~0u, s, o);
    if ((threadIdx.x & 31) == 0) sb[threadIdx.x >> 5] = s;
    __syncthreads();
    if (threadIdx.x == 0) {
        float t = 0.f;
        #pragma unroll
        for (int w = 0; w < 8; ++w) t += sb[w];
        g_d0[k] = sqrtf(t);
    }
}

// ---------------- tensor-core helpers ----------------
__device__ __forceinline__ void ldsm4t(u32& r0, u32& r1, u32& r2, u32& r3, u32 addr) {
    asm volatile("ldmatrix.sync.aligned.m8n8.x4.trans.shared.b16 {%0,%1,%2,%3}, [%4];"
                 : "=r"(r0), "=r"(r1), "=r"(r2), "=r"(r3) : "r"(addr));
}
__device__ __forceinline__ void ldsm4(u32& r0, u32& r1, u32& r2, u32& r3, u32 addr) {
    asm volatile("ldmatrix.sync.aligned.m8n8.x4.shared.b16 {%0,%1,%2,%3}, [%4];"
                 : "=r"(r0), "=r"(r1), "=r"(r2), "=r"(r3) : "r"(addr));
}
__device__ __forceinline__ void mma16816(float* c, const u32* a, const u32* b) {
    asm volatile(
        "mma.sync.aligned.m16n8k16.row.col.f32.bf16.bf16.f32 "
        "{%0,%1,%2,%3}, {%4,%5,%6,%7}, {%8,%9}, {%0,%1,%2,%3};"
        : "+f"(c[0]), "+f"(c[1]), "+f"(c[2]), "+f"(c[3])
        : "r"(a[0]), "r"(a[1]), "r"(a[2]), "r"(a[3]), "r"(b[0]), "r"(b[1]));
}

// ---------------- C = xh^T xh + xh^T xl + xl^T xh (TC, 3-stage cp.async) ------
__global__ void __launch_bounds__(256) gemmC_tc_kernel() {
    __shared__ __align__(16) char smt[3][4][16 * 256];   // 48 KB

    int rem = blockIdx.x, bi = 0, width = 16;
    while (rem >= width) { rem -= width; ++bi; --width; }
    int bj = bi + rem;

    const int tid = threadIdx.x;
    const int warp = tid >> 5, lane = tid & 31;
    const int wm = warp >> 2, wn = warp & 3;

    float acc[4][4][4];
    #pragma unroll
    for (int i = 0; i < 4; ++i)
        #pragma unroll
        for (int j = 0; j < 4; ++j)
            #pragma unroll
            for (int r = 0; r < 4; ++r) acc[i][j][r] = 0.f;

    const int ln = tid >> 4;
    const int lc = tid & 15;
    const u32 sw_off = ln * 256 + ((lc ^ (ln & 7)) << 4);
    const size_t gA = (size_t)ln * Dn + bi * 128 + lc * 8;
    const size_t gB = (size_t)ln * Dn + bj * 128 + lc * 8;

    const int q = lane >> 3, r8 = lane & 7;
    u32 aoff[4], boff[2];
    #pragma unroll
    for (int i = 0; i < 4; ++i) {
        int colh = wm * 64 + (i << 4) + ((q & 1) << 3);
        int row  = ((q >> 1) << 3) + r8;
        aoff[i] = row * 256 + ((((u32)colh >> 3) ^ (row & 7)) << 4);
    }
    #pragma unroll
    for (int p = 0; p < 2; ++p) {
        int colh = wn * 32 + (p << 4) + ((q >> 1) << 3);
        int row  = ((q & 1) << 3) + r8;
        boff[p] = row * 256 + ((((u32)colh >> 3) ^ (row & 7)) << 4);
    }

    const u32 smem_base = (u32)__cvta_generic_to_shared(&smt[0][0][0]);

    auto issue = [&](int stage, int n0) {
        size_t adv = (size_t)n0 * Dn;
        u32 d = smem_base + stage * 16384 + sw_off;
        cpasync16(d + 0 * 4096, g_xh + gA + adv);
        cpasync16(d + 1 * 4096, g_xl + gA + adv);
        cpasync16(d + 2 * 4096, g_xh + gB + adv);
        cpasync16(d + 3 * 4096, g_xl + gB + adv);
        asm volatile("cp.async.commit_group;" ::: "memory");
    };

    issue(0, 0);
    issue(1, 16);

    const int NCHUNK = Nn / 16;   // 512
    for (int ci = 0; ci < NCHUNK; ++ci) {
        asm volatile("cp.async.wait_group 1;" ::: "memory");
        __syncthreads();
        const u32 tb = smem_base + (ci % 3) * 16384;
        u32 Ah[4][4], Al[4][4], Bh[4][2], Bl[4][2];
        #pragma unroll
        for (int i = 0; i < 4; ++i) {
            ldsm4t(Ah[i][0], Ah[i][1], Ah[i][2], Ah[i][3], tb + 0 * 4096 + aoff[i]);
            ldsm4t(Al[i][0], Al[i][1], Al[i][2], Al[i][3], tb + 1 * 4096 + aoff[i]);
        }
        #pragma unroll
        for (int p = 0; p < 2; ++p) {
            ldsm4t(Bh[2 * p][0], Bh[2 * p][1], Bh[2 * p + 1][0], Bh[2 * p + 1][1],
                   tb + 2 * 4096 + boff[p]);
            ldsm4t(Bl[2 * p][0], Bl[2 * p][1], Bl[2 * p + 1][0], Bl[2 * p + 1][1],
                   tb + 3 * 4096 + boff[p]);
        }
        #pragma unroll
        for (int i = 0; i < 4; ++i)
            #pragma unroll
            for (int j = 0; j < 4; ++j) {
                mma16816(acc[i][j], Ah[i], Bh[j]);
                mma16816(acc[i][j], Ah[i], Bl[j]);
                mma16816(acc[i][j], Al[i], Bh[j]);
            }
        if (ci + 2 < NCHUNK) issue((ci + 2) % 3, (ci + 2) * 16);
    }

    const int row0 = lane >> 2, col0 = (lane & 3) * 2;
    #pragma unroll
    for (int i = 0; i < 4; ++i) {
        #pragma unroll
        for (int j = 0; j < 4; ++j) {
            int gi = bi * 128 + wm * 64 + i * 16 + row0;
            int gj = bj * 128 + wn * 32 + j * 8 + col0;
            *(float2*)(g_C + (size_t)gi * Dn + gj) =
                make_float2(acc[i][j][0], acc[i][j][1]);
            *(float2*)(g_C + (size_t)(gi + 8) * Dn + gj) =
                make_float2(acc[i][j][2], acc[i][j][3]);
            if (bi != bj) {
                g_C[(size_t)gj * Dn + gi]           = acc[i][j][0];
                g_C[(size_t)(gj + 1) * Dn + gi]     = acc[i][j][1];
                g_C[(size_t)gj * Dn + gi + 8]       = acc[i][j][2];
                g_C[(size_t)(gj + 1) * Dn + gi + 8] = acc[i][j][3];
            }
        }
    }
}

// ---------------- persistent sequential CCIPCA solve ----------------
// 512 threads, 1 row/warp. NEW: this block's 14 C-rows live in REGISTERS
// (16 float4/lane; lane l owns C[row][128i+4l..+3]) — P2 crossbar traffic
// halves (only s_a is read from smem, 16B-consecutive = conflict-free) and
// the C-row LDS latency disappears. All smem is static now (~39 KB).
__global__ void __launch_bounds__(512) solve_kernel() {
    __shared__ float s_WT[ROWS_PB * Kn];     // 14 KB
    __shared__ float s_VnT[ROWS_PB * Kn];    // 14 KB
    __shared__ __align__(16) float s_a[Dn];  // 8 KB
    __shared__ float sc3s[Kn], sc1[Kn], s_g[Kn];
    __shared__ float s_b[16], s_u[16], s_vk1[16];

    const int tid = threadIdx.x;
    const int bid = blockIdx.x;
    const int wid = tid >> 5, lane = tid & 31;
    int d_lo = bid * ROWS_PB; if (d_lo > Dn) d_lo = Dn;
    int d_hi = d_lo + ROWS_PB; if (d_hi > Dn) d_hi = Dn;
    const int nrows = d_hi - d_lo;
    unsigned gen = 0;

    // this warp's C row -> registers (coalesced: lanes 16B-consecutive)
    float4 creg[16];
    if (wid < nrows) {
        const float4* crow = (const float4*)&g_C[(size_t)(d_lo + wid) * Dn];
        #pragma unroll
        for (int i = 0; i < 16; ++i) creg[i] = crow[i * 32 + lane];
    }

    for (int k = 0; k < Kn; ++k) {
        const int pin = k & 1, pout = pin ^ 1;

        // ---------------- P1 ----------------
        float s = 0.f, c1k1 = 0.f;
        if (k > 0) {
            s = rsqrtf(g_dn2[pin]);
            c1k1 = s * g_uv[pin];
            for (int j = tid; j < k - 1; j += 512) {
                sc3s[j] = g_c3[pin][j] * s;
                sc1[j]  = g_c1[pin][j];
            }
        }
        if (bid == NBLK - 1) {   // block 147 owns 0 rows: zeroing duty
            for (int j = tid; j < Kn; j += 512) {
                g_c3[pout][j] = 0.f;
                g_c1[pout][j] = 0.f;
                g_g[j] = 0.f;
            }
            if (tid == 0) { g_dn2[pout] = 0.f; g_uv[pout] = 0.f; }
        }
        __syncthreads();

        if (k == 0) {
            for (int dd = tid; dd < nrows; dd += 512)
                g_a[d_lo + dd] = g_Vt[d_lo + dd];
        } else if (wid < nrows) {
            const int dd = wid;
            const int d = d_lo + dd;
            float u_d = s_u[dd];
            const float* wrow = &s_WT[dd * Kn];
            float sum1 = 0.f, sum2 = 0.f;
            #pragma unroll 4
            for (int j = lane; j < k - 1; j += 32) {
                float wj = wrow[j];
                sum1 += sc3s[j] * wj;
                sum2 += sc1[j] * wj;
            }
            #pragma unroll
            for (int o = 16; o; o >>= 1) {
                sum1 += __shfl_down_sync(~0u, sum1, o);
                sum2 += __shfl_down_sync(~0u, sum2, o);
            }
            if (lane == 0) {
                float vn_d = s * u_d;
                float w_d = vn_d - sum1;
                s_VnT[dd * Kn + (k - 1)] = vn_d;
                s_WT[dd * Kn + (k - 1)] = w_d;
                __nv_bfloat16 vh = __float2bfloat16(vn_d);
                g_Vh[(size_t)d * Kn + (k - 1)] = vh;
                g_Vl[(size_t)d * Kn + (k - 1)] =
                    __float2bfloat16(vn_d - __bfloat162float(vh));
                g_a[d] = g_Vt[(size_t)k * Dn + d] - sum2 - c1k1 * w_d;
            }
        }
        gbar(gen);

        // ---------------- P2: b = C a (C in registers), g_j partials ----------
        if (tid < Dn / 4)
            ((float4*)s_a)[tid] = ((const float4*)g_a)[tid];
        __syncthreads();
        if (wid < nrows) {
            const int dd = wid;
            float s0 = 0.f, s1 = 0.f, s2 = 0.f, s3 = 0.f;
            #pragma unroll
            for (int i = 0; i < 16; ++i) {
                float4 a4 = ((const float4*)s_a)[i * 32 + lane];
                s0 = fmaf(creg[i].x, a4.x, s0);
                s1 = fmaf(creg[i].y, a4.y, s1);
                s2 = fmaf(creg[i].z, a4.z, s2);
                s3 = fmaf(creg[i].w, a4.w, s3);
            }
            float sum = (s0 + s1) + (s2 + s3);
            #pragma unroll
            for (int o = 16; o; o >>= 1) sum += __shfl_down_sync(~0u, sum, o);
            if (lane == 0) s_b[dd] = sum;
        }
        __syncthreads();
        if (tid < k && nrows > 0) {
            float accg = 0.f;
            #pragma unroll 7
            for (int dd = 0; dd < nrows; ++dd)
                accg += s_WT[dd * Kn + tid] * s_b[dd];
            atomicAdd(&g_g[tid], accg);
        }
        gbar(gen);

        // ---------------- P3: u update + next-step dots ----------------
        const float hh = 0.5f / g_d0[k];
        for (int j = tid; j < k; j += 512) s_g[j] = g_g[j];
        __syncthreads();
        if (wid < nrows) {
            const int dd = wid;
            const int d = d_lo + dd;
            const float* vrow = &s_VnT[dd * Kn];
            float sumg = 0.f;
            #pragma unroll 4
            for (int j = lane; j < k; j += 32) sumg += s_g[j] * vrow[j];
            #pragma unroll
            for (int o = 16; o; o >>= 1) sumg += __shfl_down_sync(~0u, sumg, o);
            if (lane == 0) {
                float u_d = 0.5f * g_Vt[(size_t)k * Dn + d] + hh * (s_b[dd] - sumg);
                s_u[dd] = u_d;
                s_vk1[dd] = (k + 1 < Kn) ? g_Vt[(size_t)(k + 1) * Dn + d] : 0.f;
            }
        }
        __syncthreads();
        if (tid < k && nrows > 0) {
            float a3 = 0.f, a1 = 0.f;
            #pragma unroll 7
            for (int dd = 0; dd < nrows; ++dd) {
                float vv = s_VnT[dd * Kn + tid];
                a3 += vv * s_u[dd];
                a1 += vv * s_vk1[dd];
            }
            atomicAdd(&g_c3[pout][tid], a3);
            atomicAdd(&g_c1[pout][tid], a1);
        }
        if (tid == 0 && nrows > 0) {
            float d2 = 0.f, uvv = 0.f;
            #pragma unroll 7
            for (int dd = 0; dd < nrows; ++dd) {
                d2  += s_u[dd] * s_u[dd];
                uvv += s_u[dd] * s_vk1[dd];
            }
            atomicAdd(&g_dn2[pout], d2);
            atomicAdd(&g_uv[pout], uvv);
        }
        gbar(gen);
    }

    // epilogue: write vn_{K-1} (bf16 hi/lo)
    {
        const int plast = ((Kn - 1) & 1) ^ 1;
        float sfin = rsqrtf(g_dn2[plast]);
        for (int dd = tid; dd < nrows; dd += 512) {
            float vn_d = sfin * s_u[dd];
            __nv_bfloat16 vh = __float2bfloat16(vn_d);
            g_Vh[(size_t)(d_lo + dd) * Kn + (Kn - 1)] = vh;
            g_Vl[(size_t)(d_lo + dd) * Kn + (Kn - 1)] =
                __float2bfloat16(vn_d - __bfloat162float(vh));
        }
    }

    __syncthreads();
    if (tid == 0) {
        __threadfence();
        if (atomicAdd(&g_done, 1u) == (unsigned)(gridDim.x - 1)) {
            g_done = 0u;
            g_barcnt = 0u;
            __threadfence();
        }
    }
}

// ---------------- out = x @ Vn (tensor cores, bf16 3-term split) --------------
__global__ void __launch_bounds__(256, 2) gemmOut_tc_kernel(float* __restrict__ out) {
    __shared__ __align__(16) u16 sa[2][2][128][24];
    __shared__ __align__(16) u16 sb[2][2][16][64];

    const int bm = blockIdx.x >> 2;
    const int bj = blockIdx.x & 3;
    const int tid = threadIdx.x;
    const int warp = tid >> 5, lane = tid & 31;
    const int wm = warp >> 2, wn = warp & 3;
    const int m0 = bm * 128;

    float acc[4][2][4];
    #pragma unroll
    for (int i = 0; i < 4; ++i)
        #pragma unroll
        for (int j = 0; j < 2; ++j)
            #pragma unroll
            for (int r = 0; r < 4; ++r) acc[i][j][r] = 0.f;

    const int am = tid >> 1, ac = tid & 1;
    const size_t gxa = (size_t)(m0 + am) * Dn + ac * 8;
    const int bmat = tid >> 7;
    const int brr = (tid >> 3) & 15;
    const int bcc = tid & 7;
    const int bsw = (bcc ^ (brr & 7)) * 8;
    const size_t gvb = (size_t)brr * Kn + bj * 64 + bcc * 8;
    const __nv_bfloat16* vsrc = bmat ? g_Vl : g_Vh;

    const int q = lane >> 3, r8 = lane & 7;
    u32 aoff[4];
    #pragma unroll
    for (int i = 0; i < 4; ++i) {
        int row = wm * 64 + i * 16 + ((q & 1) << 3) + r8;
        aoff[i] = (u32)row * 48 + ((u32)(q >> 1) << 4);
    }
    u32 boff;
    {
        int bcol = wn * 16 + ((q >> 1) << 3);
        int brow = ((q & 1) << 3) + r8;
        boff = (u32)brow * 128 + ((((u32)bcol >> 3) ^ (brow & 7)) << 4);
    }
    const u32 sa_base = (u32)__cvta_generic_to_shared(&sa[0][0][0][0]);
    const u32 sb_base = (u32)__cvta_generic_to_shared(&sb[0][0][0][0]);
    const u32 SA_MAT = 128 * 48;
    const u32 SB_MAT = 16 * 128;

    uint4 pah, pal, pbv;
    pah = *(const uint4*)(g_xh + gxa);
    pal = *(const uint4*)(g_xl + gxa);
    pbv = *(const uint4*)(vsrc + gvb);
    *(uint4*)&sa[0][0][am][ac * 8] = pah;
    *(uint4*)&sa[0][1][am][ac * 8] = pal;
    *(uint4*)&sb[0][bmat][brr][bsw] = pbv;
    __syncthreads();

    int buf = 0;
    for (int d0 = 0; d0 < Dn; d0 += 16) {
        const bool more = (d0 + 16 < Dn);
        if (more) {
            pah = *(const uint4*)(g_xh + gxa + (d0 + 16));
            pal = *(const uint4*)(g_xl + gxa + (d0 + 16));
            pbv = *(const uint4*)(vsrc + gvb + (size_t)(d0 + 16) * Kn);
        }
        const u32 ab = sa_base + buf * (2 * SA_MAT);
        const u32 bb = sb_base + buf * (2 * SB_MAT);
        u32 Ah[4][4], Al[4][4], Bh[2][2], Bl[2][2];
        #pragma unroll
        for (int i = 0; i < 4; ++i) {
            ldsm4(Ah[i][0], Ah[i][1], Ah[i][2], Ah[i][3], ab + aoff[i]);
            ldsm4(Al[i][0], Al[i][1], Al[i][2], Al[i][3], ab + SA_MAT + aoff[i]);
        }
        ldsm4t(Bh[0][0], Bh[0][1], Bh[1][0], Bh[1][1], bb + boff);
        ldsm4t(Bl[0][0], Bl[0][1], Bl[1][0], Bl[1][1], bb + SB_MAT + boff);
        #pragma unroll
        for (int i = 0; i < 4; ++i)
            #pragma unroll
            for (int j = 0; j < 2; ++j) {
                mma16816(acc[i][j], Ah[i], Bh[j]);
                mma16816(acc[i][j], Ah[i], Bl[j]);
                mma16816(acc[i][j], Al[i], Bh[j]);
            }
        if (more) {
            int nb = buf ^ 1;
            *(uint4*)&sa[nb][0][am][ac * 8] = pah;
            *(uint4*)&sa[nb][1][am][ac * 8] = pal;
            *(uint4*)&sb[nb][bmat][brr][bsw] = pbv;
        }
        __syncthreads();
        buf ^= 1;
    }

    const int row0 = lane >> 2, col0 = (lane & 3) * 2;
    #pragma unroll
    for (int i = 0; i < 4; ++i)
        #pragma unroll
        for (int j = 0; j < 2; ++j) {
            int gi = m0 + wm * 64 + i * 16 + row0;
            int gj = bj * 64 + wn * 16 + j * 8 + col0;
            *(float2*)(out + (size_t)gi * Kn + gj) =
                make_float2(acc[i][j][0], acc[i][j][1]);
            *(float2*)(out + (size_t)(gi + 8) * Kn + gj) =
                make_float2(acc[i][j][2], acc[i][j][3]);
        }
}

// ---------------- launch ----------------
extern "C" void kernel_launch(void* const* d_in, const int* in_sizes, int n_in,
                              void* d_out, int out_size) {
    const float* x  = (const float*)d_in[0];
    const float* V0 = (const float*)d_in[1];
    if (n_in >= 2 && in_sizes[0] == Dn * Kn && in_sizes[1] == Nn * Dn) {
        const float* t = x; x = V0; V0 = t;
    }
    float* out = (float*)d_out;

    splitx_kernel<<<2048, 256>>>(x);
    prep_kernel<<<Kn, 256>>>(V0);
    gemmC_tc_kernel<<<136, 256>>>();
    solve_kernel<<<NBLK, 512>>>();
    gemmOut_tc_kernel<<<256, 256>>>(out);
}